// round 1
// baseline (speedup 1.0000x reference)
#include <cuda_runtime.h>
#include <math.h>

#define BB 2
#define TT 1024
#define DIN 2048
#define NH 32
#define HKV 8
#define HD 128
#define LPREV 1024
#define LFULL 2048

// ---------------- scratch (static device globals; no runtime alloc) ----------
__device__ float g_qraw[(size_t)BB * TT * NH * HD];    // 2048 x 4096
__device__ float g_kraw[(size_t)BB * TT * HKV * HD];   // 2048 x 1024
__device__ float g_vraw[(size_t)BB * TT * HKV * HD];   // 2048 x 1024
__device__ float g_qh[(size_t)BB * NH * TT * HD];      // [B,H,T,HD]
__device__ float g_ctx[(size_t)BB * TT * NH * HD];     // 2048 x 4096
// fallback KV buffers in case d_out only holds `out`
__device__ float g_fk[(size_t)BB * HKV * LFULL * HD];
__device__ float g_fv[(size_t)BB * HKV * LFULL * HD];

// ---------------- generic SGEMM: C[M,N] = A[M,K] * W[N,K]^T ------------------
// M,N multiples of 128; K multiple of 16. 256 threads, 8x8 per thread.
__global__ __launch_bounds__(256) void sgemm_nt(const float* __restrict__ A,
                                                const float* __restrict__ W,
                                                float* __restrict__ C,
                                                int M, int N, int K) {
  __shared__ float As[16][128];
  __shared__ float Bs[16][128];
  const int tid = threadIdx.x;
  const int m0 = blockIdx.y * 128, n0 = blockIdx.x * 128;
  const int tx = tid & 15, ty = tid >> 4;
  const int tm = ty * 8, tn = tx * 8;
  const int lr = tid >> 2, lc = (tid & 3) * 4;

  const float* Ap = A + (size_t)(m0 + lr) * K + lc;
  const float* Wp = W + (size_t)(n0 + lr) * K + lc;

  float acc[8][8];
#pragma unroll
  for (int i = 0; i < 8; i++)
#pragma unroll
    for (int j = 0; j < 8; j++) acc[i][j] = 0.f;

  for (int k0 = 0; k0 < K; k0 += 16) {
    float4 a0 = *(const float4*)(Ap + k0);
    float4 a1 = *(const float4*)(Ap + (size_t)64 * K + k0);
    float4 w0 = *(const float4*)(Wp + k0);
    float4 w1 = *(const float4*)(Wp + (size_t)64 * K + k0);
    __syncthreads();
    As[lc + 0][lr] = a0.x; As[lc + 1][lr] = a0.y;
    As[lc + 2][lr] = a0.z; As[lc + 3][lr] = a0.w;
    As[lc + 0][lr + 64] = a1.x; As[lc + 1][lr + 64] = a1.y;
    As[lc + 2][lr + 64] = a1.z; As[lc + 3][lr + 64] = a1.w;
    Bs[lc + 0][lr] = w0.x; Bs[lc + 1][lr] = w0.y;
    Bs[lc + 2][lr] = w0.z; Bs[lc + 3][lr] = w0.w;
    Bs[lc + 0][lr + 64] = w1.x; Bs[lc + 1][lr + 64] = w1.y;
    Bs[lc + 2][lr + 64] = w1.z; Bs[lc + 3][lr + 64] = w1.w;
    __syncthreads();
#pragma unroll
    for (int kk = 0; kk < 16; kk++) {
      float ra[8], rb[8];
      *(float4*)&ra[0] = *(const float4*)&As[kk][tm];
      *(float4*)&ra[4] = *(const float4*)&As[kk][tm + 4];
      *(float4*)&rb[0] = *(const float4*)&Bs[kk][tn];
      *(float4*)&rb[4] = *(const float4*)&Bs[kk][tn + 4];
#pragma unroll
      for (int i = 0; i < 8; i++)
#pragma unroll
        for (int j = 0; j < 8; j++) acc[i][j] += ra[i] * rb[j];
    }
  }
#pragma unroll
  for (int i = 0; i < 8; i++) {
    float4 o0 = make_float4(acc[i][0], acc[i][1], acc[i][2], acc[i][3]);
    float4 o1 = make_float4(acc[i][4], acc[i][5], acc[i][6], acc[i][7]);
    *(float4*)(C + (size_t)(m0 + tm + i) * N + n0 + tn) = o0;
    *(float4*)(C + (size_t)(m0 + tm + i) * N + n0 + tn + 4) = o1;
  }
}

// ---------------- copy prev_k/prev_v into full_k/full_v ----------------------
__global__ void copy_prev(const float4* __restrict__ pk, const float4* __restrict__ pv,
                          float4* __restrict__ fk, float4* __restrict__ fv) {
  int i = blockIdx.x * blockDim.x + threadIdx.x;
  const int total = BB * HKV * LPREV * HD / 4;  // 524288
  if (i >= total) return;
  const int per = LPREV * HD / 4;    // 32768
  const int dper = LFULL * HD / 4;   // 65536
  int bh = i / per, off = i - bh * per;
  fk[(size_t)bh * dper + off] = pk[i];
  fv[(size_t)bh * dper + off] = pv[i];
}

// ---------------- RMSNorm + RoPE + scatter -----------------------------------
// grid: (B*T, H + 2*HKV), 128 threads. role<H: q; role<H+HKV: k; else v.
__global__ void norm_rope_kernel(const float* __restrict__ cosT,
                                 const float* __restrict__ sinT,
                                 const float* __restrict__ qw,
                                 const float* __restrict__ kw,
                                 float* __restrict__ fullk,
                                 float* __restrict__ fullv) {
  int bt = blockIdx.x;
  int b = bt >> 10, t = bt & 1023;
  int role = blockIdx.y;
  int d = threadIdx.x;
  __shared__ float red[128];
  __shared__ float row[128];
  int pos = LPREV + t;

  if (role < NH) {
    int h = role;
    float v = g_qraw[(size_t)bt * (NH * HD) + h * HD + d];
    red[d] = v * v;
    __syncthreads();
#pragma unroll
    for (int s = 64; s > 0; s >>= 1) {
      if (d < s) red[d] += red[d + s];
      __syncthreads();
    }
    float inv = rsqrtf(red[0] * (1.0f / HD) + 1e-6f);
    float xn = v * inv * qw[d];
    row[d] = xn;
    __syncthreads();
    float rot = (d < 64) ? -row[d + 64] : row[d - 64];
    float o = xn * cosT[pos * HD + d] + rot * sinT[pos * HD + d];
    g_qh[(((size_t)b * NH + h) * TT + t) * HD + d] = o;
  } else if (role < NH + HKV) {
    int h = role - NH;
    float v = g_kraw[(size_t)bt * (HKV * HD) + h * HD + d];
    red[d] = v * v;
    __syncthreads();
#pragma unroll
    for (int s = 64; s > 0; s >>= 1) {
      if (d < s) red[d] += red[d + s];
      __syncthreads();
    }
    float inv = rsqrtf(red[0] * (1.0f / HD) + 1e-6f);
    float xn = v * inv * kw[d];
    row[d] = xn;
    __syncthreads();
    float rot = (d < 64) ? -row[d + 64] : row[d - 64];
    float o = xn * cosT[pos * HD + d] + rot * sinT[pos * HD + d];
    fullk[(((size_t)b * HKV + h) * LFULL + LPREV + t) * HD + d] = o;
  } else {
    int h = role - NH - HKV;
    fullv[(((size_t)b * HKV + h) * LFULL + LPREV + t) * HD + d] =
        g_vraw[(size_t)bt * (HKV * HD) + h * HD + d];
  }
}

// ---------------- flash attention (fp32, online softmax) ---------------------
#define TQ 64
#define SK 32
#define QP 33  // float4 pitch per 128-float row (+16B pad, conflict spread)

__global__ __launch_bounds__(256) void attn_kernel(const float* __restrict__ fullk,
                                                   const float* __restrict__ fullv) {
  extern __shared__ float4 sm4[];
  float4* Qs = sm4;                 // TQ*QP
  float4* Ks = Qs + TQ * QP;        // SK*QP
  float4* Vs = Ks + SK * QP;        // SK*QP
  float* P = (float*)(Vs + SK * QP);  // TQ*SK floats

  const int tid = threadIdx.x;
  const int bx = blockIdx.x;
  const int qt = bx & 15, h = (bx >> 4) & 31, b = bx >> 9;
  const int q0 = qt * TQ;
  const int qi = tid >> 2, dg = tid & 3;

  const float scale = 0.08838834764831845f;  // 1/sqrt(128)

  // load Q tile (scaled)
  const float4* qg = (const float4*)(g_qh + (((size_t)b * NH + h) * TT + q0) * HD);
  for (int i = tid; i < TQ * 32; i += 256) {
    int r = i >> 5, c = i & 31;
    float4 v = qg[r * 32 + c];
    v.x *= scale; v.y *= scale; v.z *= scale; v.w *= scale;
    Qs[r * QP + c] = v;
  }

  const float4* kg = (const float4*)(fullk + (((size_t)b * HKV + (h >> 2)) * LFULL) * HD);
  const float4* vg = (const float4*)(fullv + (((size_t)b * HKV + (h >> 2)) * LFULL) * HD);

  float4 acc[8];
#pragma unroll
  for (int i = 0; i < 8; i++) acc[i] = make_float4(0.f, 0.f, 0.f, 0.f);
  float m = -1e30f, l = 0.f;
  const int jlimit = LPREV + q0 + TQ;
  const int tlim = LPREV + q0 + qi;  // allowed: j <= tlim

  for (int j0 = 0; j0 < jlimit; j0 += SK) {
    __syncthreads();
    for (int i = tid; i < SK * 32; i += 256) {
      int r = i >> 5, c = i & 31;
      Ks[r * QP + c] = kg[(size_t)(j0 + r) * 32 + c];
      Vs[r * QP + c] = vg[(size_t)(j0 + r) * 32 + c];
    }
    __syncthreads();

    // scores: this thread handles q-row qi, keys j = jj*4 + dg
    float s[8];
#pragma unroll
    for (int jj = 0; jj < 8; jj++) s[jj] = 0.f;
    const float4* qr = Qs + qi * QP;
#pragma unroll 8
    for (int c = 0; c < 32; c++) {
      float4 a = qr[c];
#pragma unroll
      for (int jj = 0; jj < 8; jj++) {
        float4 kk4 = Ks[(jj * 4 + dg) * QP + c];
        s[jj] += a.x * kk4.x + a.y * kk4.y + a.z * kk4.z + a.w * kk4.w;
      }
    }
#pragma unroll
    for (int jj = 0; jj < 8; jj++) {
      int jglob = j0 + jj * 4 + dg;
      if (jglob > tlim) s[jj] = -1e30f;
    }

    float rmax = s[0];
#pragma unroll
    for (int jj = 1; jj < 8; jj++) rmax = fmaxf(rmax, s[jj]);
    rmax = fmaxf(rmax, __shfl_xor_sync(0xffffffffu, rmax, 1));
    rmax = fmaxf(rmax, __shfl_xor_sync(0xffffffffu, rmax, 2));
    float nm = fmaxf(m, rmax);

    float psum = 0.f;
#pragma unroll
    for (int jj = 0; jj < 8; jj++) {
      float p = __expf(s[jj] - nm);
      psum += p;
      P[qi * 32 + jj * 4 + dg] = p;
    }
    psum += __shfl_xor_sync(0xffffffffu, psum, 1);
    psum += __shfl_xor_sync(0xffffffffu, psum, 2);
    float corr = __expf(m - nm);
    l = l * corr + psum;
    m = nm;
    __syncwarp();

#pragma unroll
    for (int i = 0; i < 8; i++) {
      acc[i].x *= corr; acc[i].y *= corr; acc[i].z *= corr; acc[i].w *= corr;
    }
#pragma unroll 4
    for (int j = 0; j < SK; j++) {
      float p = P[qi * 32 + j];
      const float4* vr = Vs + j * QP;
#pragma unroll
      for (int dd = 0; dd < 8; dd++) {
        float4 v4 = vr[dg + dd * 4];
        acc[dd].x += p * v4.x; acc[dd].y += p * v4.y;
        acc[dd].z += p * v4.z; acc[dd].w += p * v4.w;
      }
    }
  }

  float invl = 1.f / l;
  float* op = g_ctx + ((size_t)(b * TT + q0 + qi)) * (NH * HD) + h * HD;
#pragma unroll
  for (int dd = 0; dd < 8; dd++) {
    float4 o = acc[dd];
    o.x *= invl; o.y *= invl; o.z *= invl; o.w *= invl;
    *(float4*)(op + dg * 4 + dd * 16) = o;
  }
}

// ---------------- launch ------------------------------------------------------
extern "C" void kernel_launch(void* const* d_in, const int* in_sizes, int n_in,
                              void* d_out, int out_size) {
  const float* x = (const float*)d_in[0];
  // d_in[1] = attn_mask (causal, recomputed), d_in[4] = position_ids (deterministic)
  const float* cosT = (const float*)d_in[2];
  const float* sinT = (const float*)d_in[3];
  const float* prev_k = (const float*)d_in[5];
  const float* prev_v = (const float*)d_in[6];
  const float* Wq = (const float*)d_in[7];
  const float* Wk = (const float*)d_in[8];
  const float* Wv = (const float*)d_in[9];
  const float* Wo = (const float*)d_in[10];
  const float* qw = (const float*)d_in[11];
  const float* kw = (const float*)d_in[12];

  float* out = (float*)d_out;
  const size_t out_elems = (size_t)BB * TT * DIN;              // 4194304
  const size_t kv_elems = (size_t)BB * HKV * LFULL * HD;       // 4194304

  float* fullk;
  float* fullv;
  if ((size_t)out_size >= out_elems + 2 * kv_elems) {
    fullk = out + out_elems;
    fullv = fullk + kv_elems;
  } else {
    cudaGetSymbolAddress((void**)&fullk, g_fk);
    cudaGetSymbolAddress((void**)&fullv, g_fv);
  }

  float *qraw, *kraw, *vraw, *ctx;
  cudaGetSymbolAddress((void**)&qraw, g_qraw);
  cudaGetSymbolAddress((void**)&kraw, g_kraw);
  cudaGetSymbolAddress((void**)&vraw, g_vraw);
  cudaGetSymbolAddress((void**)&ctx, g_ctx);

  const int M = BB * TT;  // 2048

  // QKV projections
  sgemm_nt<<<dim3((NH * HD) / 128, M / 128), 256>>>(x, Wq, qraw, M, NH * HD, DIN);
  sgemm_nt<<<dim3((HKV * HD) / 128, M / 128), 256>>>(x, Wk, kraw, M, HKV * HD, DIN);
  sgemm_nt<<<dim3((HKV * HD) / 128, M / 128), 256>>>(x, Wv, vraw, M, HKV * HD, DIN);

  // KV-cache prefix copy
  copy_prev<<<2048, 256>>>((const float4*)prev_k, (const float4*)prev_v,
                           (float4*)fullk, (float4*)fullv);

  // RMSNorm + RoPE + scatter (writes g_qh and tail of fullk/fullv)
  norm_rope_kernel<<<dim3(BB * TT, NH + 2 * HKV), 128>>>(cosT, sinT, qw, kw, fullk, fullv);

  // flash attention
  const int ATTN_SMEM = (TQ * QP + 2 * SK * QP) * 16 + TQ * SK * 4;  // 75776 B
  cudaFuncSetAttribute(attn_kernel, cudaFuncAttributeMaxDynamicSharedMemorySize, ATTN_SMEM);
  attn_kernel<<<BB * NH * (TT / TQ), 256, ATTN_SMEM>>>(fullk, fullv);

  // output projection into d_out
  sgemm_nt<<<dim3(DIN / 128, M / 128), 256>>>(ctx, Wo, out, M, DIN, NH * HD);
}

// round 2
// speedup vs baseline: 1.5063x; 1.5063x over previous
#include <cuda_runtime.h>
#include <math.h>

#define BB 2
#define TT 1024
#define DIN 2048
#define NH 32
#define HKV 8
#define HD 128
#define LPREV 1024
#define LFULL 2048

// ---------------- scratch (static device globals; no runtime alloc) ----------
__device__ float g_qraw[(size_t)BB * TT * NH * HD];    // 2048 x 4096
__device__ float g_kraw[(size_t)BB * TT * HKV * HD];   // 2048 x 1024
__device__ float g_vraw[(size_t)BB * TT * HKV * HD];   // 2048 x 1024
__device__ float g_qh[(size_t)BB * NH * TT * HD];      // [B,H,T,HD]
__device__ float g_ctx[(size_t)BB * TT * NH * HD];     // 2048 x 4096
// fallback KV buffers in case d_out only holds `out`
__device__ float g_fk[(size_t)BB * HKV * LFULL * HD];
__device__ float g_fv[(size_t)BB * HKV * LFULL * HD];

// ---------------- SGEMM v2: C[M,N] = A[M,K] * W[N,K]^T -----------------------
// 128x128 tile, K-chunk 16, double smem buffer + register prefetch.
__global__ __launch_bounds__(256, 2) void sgemm_nt(const float* __restrict__ A,
                                                   const float* __restrict__ W,
                                                   float* __restrict__ C,
                                                   int M, int N, int K) {
  __shared__ float As[2][16][128];
  __shared__ float Bs[2][16][128];
  const int tid = threadIdx.x;
  const int m0 = blockIdx.y * 128, n0 = blockIdx.x * 128;
  const int tx = tid & 15, ty = tid >> 4;
  const int tm = ty * 8, tn = tx * 8;
  const int lr = tid >> 2, lc = (tid & 3) * 4;

  const float* Ap = A + (size_t)(m0 + lr) * K + lc;
  const float* Wp = W + (size_t)(n0 + lr) * K + lc;

  float acc[8][8];
#pragma unroll
  for (int i = 0; i < 8; i++)
#pragma unroll
    for (int j = 0; j < 8; j++) acc[i][j] = 0.f;

  float4 pa0, pa1, pb0, pb1;
  pa0 = *(const float4*)(Ap);
  pa1 = *(const float4*)(Ap + (size_t)64 * K);
  pb0 = *(const float4*)(Wp);
  pb1 = *(const float4*)(Wp + (size_t)64 * K);

#define STORE_TILE(buf)                                                      \
  do {                                                                       \
    As[buf][lc + 0][lr] = pa0.x; As[buf][lc + 1][lr] = pa0.y;               \
    As[buf][lc + 2][lr] = pa0.z; As[buf][lc + 3][lr] = pa0.w;               \
    As[buf][lc + 0][lr + 64] = pa1.x; As[buf][lc + 1][lr + 64] = pa1.y;     \
    As[buf][lc + 2][lr + 64] = pa1.z; As[buf][lc + 3][lr + 64] = pa1.w;     \
    Bs[buf][lc + 0][lr] = pb0.x; Bs[buf][lc + 1][lr] = pb0.y;               \
    Bs[buf][lc + 2][lr] = pb0.z; Bs[buf][lc + 3][lr] = pb0.w;               \
    Bs[buf][lc + 0][lr + 64] = pb1.x; Bs[buf][lc + 1][lr + 64] = pb1.y;     \
    Bs[buf][lc + 2][lr + 64] = pb1.z; Bs[buf][lc + 3][lr + 64] = pb1.w;     \
  } while (0)

  STORE_TILE(0);
  __syncthreads();

  const int nk = K >> 4;
  for (int kt = 0; kt < nk; kt++) {
    const int cur = kt & 1;
    if (kt + 1 < nk) {
      const int k0 = (kt + 1) << 4;
      pa0 = *(const float4*)(Ap + k0);
      pa1 = *(const float4*)(Ap + (size_t)64 * K + k0);
      pb0 = *(const float4*)(Wp + k0);
      pb1 = *(const float4*)(Wp + (size_t)64 * K + k0);
    }
#pragma unroll
    for (int kk = 0; kk < 16; kk++) {
      float ra[8], rb[8];
      *(float4*)&ra[0] = *(const float4*)&As[cur][kk][tm];
      *(float4*)&ra[4] = *(const float4*)&As[cur][kk][tm + 4];
      *(float4*)&rb[0] = *(const float4*)&Bs[cur][kk][tn];
      *(float4*)&rb[4] = *(const float4*)&Bs[cur][kk][tn + 4];
#pragma unroll
      for (int i = 0; i < 8; i++)
#pragma unroll
        for (int j = 0; j < 8; j++) acc[i][j] += ra[i] * rb[j];
    }
    if (kt + 1 < nk) STORE_TILE(cur ^ 1);
    __syncthreads();
  }
#undef STORE_TILE

#pragma unroll
  for (int i = 0; i < 8; i++) {
    float4 o0 = make_float4(acc[i][0], acc[i][1], acc[i][2], acc[i][3]);
    float4 o1 = make_float4(acc[i][4], acc[i][5], acc[i][6], acc[i][7]);
    *(float4*)(C + (size_t)(m0 + tm + i) * N + n0 + tn) = o0;
    *(float4*)(C + (size_t)(m0 + tm + i) * N + n0 + tn + 4) = o1;
  }
}

// ---------------- copy prev_k/prev_v into full_k/full_v ----------------------
__global__ void copy_prev(const float4* __restrict__ pk, const float4* __restrict__ pv,
                          float4* __restrict__ fk, float4* __restrict__ fv) {
  int i = blockIdx.x * blockDim.x + threadIdx.x;
  const int total = BB * HKV * LPREV * HD / 4;  // 524288
  if (i >= total) return;
  const int per = LPREV * HD / 4;    // 32768
  const int dper = LFULL * HD / 4;   // 65536
  int bh = i / per, off = i - bh * per;
  fk[(size_t)bh * dper + off] = pk[i];
  fv[(size_t)bh * dper + off] = pv[i];
}

// ---------------- RMSNorm + RoPE + scatter -----------------------------------
__global__ void norm_rope_kernel(const float* __restrict__ cosT,
                                 const float* __restrict__ sinT,
                                 const float* __restrict__ qw,
                                 const float* __restrict__ kw,
                                 float* __restrict__ fullk,
                                 float* __restrict__ fullv) {
  int bt = blockIdx.x;
  int b = bt >> 10, t = bt & 1023;
  int role = blockIdx.y;
  int d = threadIdx.x;
  __shared__ float red[128];
  __shared__ float row[128];
  int pos = LPREV + t;

  if (role < NH) {
    int h = role;
    float v = g_qraw[(size_t)bt * (NH * HD) + h * HD + d];
    red[d] = v * v;
    __syncthreads();
#pragma unroll
    for (int s = 64; s > 0; s >>= 1) {
      if (d < s) red[d] += red[d + s];
      __syncthreads();
    }
    float inv = rsqrtf(red[0] * (1.0f / HD) + 1e-6f);
    float xn = v * inv * qw[d];
    row[d] = xn;
    __syncthreads();
    float rot = (d < 64) ? -row[d + 64] : row[d - 64];
    float o = xn * cosT[pos * HD + d] + rot * sinT[pos * HD + d];
    g_qh[(((size_t)b * NH + h) * TT + t) * HD + d] = o;
  } else if (role < NH + HKV) {
    int h = role - NH;
    float v = g_kraw[(size_t)bt * (HKV * HD) + h * HD + d];
    red[d] = v * v;
    __syncthreads();
#pragma unroll
    for (int s = 64; s > 0; s >>= 1) {
      if (d < s) red[d] += red[d + s];
      __syncthreads();
    }
    float inv = rsqrtf(red[0] * (1.0f / HD) + 1e-6f);
    float xn = v * inv * kw[d];
    row[d] = xn;
    __syncthreads();
    float rot = (d < 64) ? -row[d + 64] : row[d - 64];
    float o = xn * cosT[pos * HD + d] + rot * sinT[pos * HD + d];
    fullk[(((size_t)b * HKV + h) * LFULL + LPREV + t) * HD + d] = o;
  } else {
    int h = role - NH - HKV;
    fullv[(((size_t)b * HKV + h) * LFULL + LPREV + t) * HD + d] =
        g_vraw[(size_t)bt * (HKV * HD) + h * HD + d];
  }
}

// ---------------- flash attention v2 (register-blocked, fp32) ----------------
// CTA: 256 threads, TQ=64 queries, SK=64 keys per tile.
// Phase1: thread (qg,kg) computes 4q x 4k scores (k strided by 16).
// Phase2: thread (qg,dg2) accumulates 4q x 8d of O (d cols dg2*4 and 64+dg2*4).
#define TQ 64
#define SK 64
#define DP 33  // float4 pitch for 128-float rows
#define PP 17  // float4 pitch for 64-float rows (P)

__global__ __launch_bounds__(256, 1) void attn_kernel(const float* __restrict__ fullk,
                                                      const float* __restrict__ fullv) {
  extern __shared__ float smemf[];
  float4* Qs = (float4*)smemf;        // TQ*DP
  float4* Ks = Qs + TQ * DP;          // SK*DP
  float4* Vs = Ks + SK * DP;          // SK*DP
  float4* Ps = Vs + SK * DP;          // TQ*PP
  float* Pf = (float*)Ps;
  float* Ms = (float*)(Ps + TQ * PP);
  float* Ls = Ms + TQ;
  float* Cs = Ls + TQ;

  const int tid = threadIdx.x;
  const int bx = blockIdx.x;
  const int qt = bx & 15, h = (bx >> 4) & 31, b = bx >> 9;
  const int q0 = qt * TQ;
  const int kg = tid & 15;   // phase1 k lane
  const int qg = tid >> 4;   // q group (both phases)
  const int dg2 = tid & 15;  // phase2 d lane

  const float scale = 0.08838834764831845f;  // 1/sqrt(128)

  // load Q tile (pre-scaled)
  const float4* qgp = (const float4*)(g_qh + (((size_t)b * NH + h) * TT + q0) * HD);
  for (int i = tid; i < TQ * 32; i += 256) {
    int r = i >> 5, c = i & 31;
    float4 v = qgp[r * 32 + c];
    v.x *= scale; v.y *= scale; v.z *= scale; v.w *= scale;
    Qs[r * DP + c] = v;
  }
  if (tid < TQ) { Ms[tid] = -1e30f; Ls[tid] = 0.f; }

  const float4* kgp = (const float4*)(fullk + (((size_t)b * HKV + (h >> 2)) * LFULL) * HD);
  const float4* vgp = (const float4*)(fullv + (((size_t)b * HKV + (h >> 2)) * LFULL) * HD);

  float4 acc[4][2];
#pragma unroll
  for (int i = 0; i < 4; i++) {
    acc[i][0] = make_float4(0.f, 0.f, 0.f, 0.f);
    acc[i][1] = make_float4(0.f, 0.f, 0.f, 0.f);
  }

  const int diag = LPREV + q0;
  const int ntiles = (diag + TQ) / SK;

  for (int jt = 0; jt < ntiles; jt++) {
    const int j0 = jt * SK;
    __syncthreads();
    for (int i = tid; i < SK * 32; i += 256) {
      int r = i >> 5, c = i & 31;
      Ks[r * DP + c] = kgp[(size_t)(j0 + r) * 32 + c];
      Vs[r * DP + c] = vgp[(size_t)(j0 + r) * 32 + c];
    }
    __syncthreads();

    // ---- phase 1: scores ----
    float s[4][4];
#pragma unroll
    for (int i = 0; i < 4; i++)
#pragma unroll
      for (int j = 0; j < 4; j++) s[i][j] = 0.f;

#pragma unroll 4
    for (int c = 0; c < 32; c++) {
      float4 qv[4], kv[4];
#pragma unroll
      for (int i = 0; i < 4; i++) qv[i] = Qs[(qg * 4 + i) * DP + c];
#pragma unroll
      for (int j = 0; j < 4; j++) kv[j] = Ks[(kg + 16 * j) * DP + c];
#pragma unroll
      for (int i = 0; i < 4; i++)
#pragma unroll
        for (int j = 0; j < 4; j++)
          s[i][j] += qv[i].x * kv[j].x + qv[i].y * kv[j].y +
                     qv[i].z * kv[j].z + qv[i].w * kv[j].w;
    }

    if (j0 == diag) {  // diagonal tile: mask kk > qrow
#pragma unroll
      for (int i = 0; i < 4; i++)
#pragma unroll
        for (int j = 0; j < 4; j++)
          if (kg + 16 * j > qg * 4 + i) s[i][j] = -1e30f;
    }

    // ---- softmax (per q-row, 16 lanes per row-group) ----
#pragma unroll
    for (int i = 0; i < 4; i++) {
      const int q = qg * 4 + i;
      float rmax = fmaxf(fmaxf(s[i][0], s[i][1]), fmaxf(s[i][2], s[i][3]));
      rmax = fmaxf(rmax, __shfl_xor_sync(0xffffffffu, rmax, 1));
      rmax = fmaxf(rmax, __shfl_xor_sync(0xffffffffu, rmax, 2));
      rmax = fmaxf(rmax, __shfl_xor_sync(0xffffffffu, rmax, 4));
      rmax = fmaxf(rmax, __shfl_xor_sync(0xffffffffu, rmax, 8));
      float mo = Ms[q];
      float nm = fmaxf(mo, rmax);
      float psum = 0.f;
#pragma unroll
      for (int j = 0; j < 4; j++) {
        float p = __expf(s[i][j] - nm);
        psum += p;
        Pf[q * (PP * 4) + kg + 16 * j] = p;
      }
      psum += __shfl_xor_sync(0xffffffffu, psum, 1);
      psum += __shfl_xor_sync(0xffffffffu, psum, 2);
      psum += __shfl_xor_sync(0xffffffffu, psum, 4);
      psum += __shfl_xor_sync(0xffffffffu, psum, 8);
      if (kg == 0) {
        float corr = __expf(mo - nm);
        Cs[q] = corr;
        Ls[q] = Ls[q] * corr + psum;
        Ms[q] = nm;
      }
    }
    __syncthreads();

    // ---- phase 2: O += P * V ----
    float corr[4];
#pragma unroll
    for (int i = 0; i < 4; i++) corr[i] = Cs[qg * 4 + i];
#pragma unroll
    for (int i = 0; i < 4; i++) {
      acc[i][0].x *= corr[i]; acc[i][0].y *= corr[i];
      acc[i][0].z *= corr[i]; acc[i][0].w *= corr[i];
      acc[i][1].x *= corr[i]; acc[i][1].y *= corr[i];
      acc[i][1].z *= corr[i]; acc[i][1].w *= corr[i];
    }
#pragma unroll 4
    for (int kc = 0; kc < 16; kc++) {
      float4 p4[4];
#pragma unroll
      for (int i = 0; i < 4; i++) p4[i] = Ps[(qg * 4 + i) * PP + kc];
#pragma unroll
      for (int kk = 0; kk < 4; kk++) {
        float4 v0 = Vs[(kc * 4 + kk) * DP + dg2];
        float4 v1 = Vs[(kc * 4 + kk) * DP + dg2 + 16];
#pragma unroll
        for (int i = 0; i < 4; i++) {
          float p = ((const float*)&p4[i])[kk];
          acc[i][0].x += p * v0.x; acc[i][0].y += p * v0.y;
          acc[i][0].z += p * v0.z; acc[i][0].w += p * v0.w;
          acc[i][1].x += p * v1.x; acc[i][1].y += p * v1.y;
          acc[i][1].z += p * v1.z; acc[i][1].w += p * v1.w;
        }
      }
    }
  }

  // ---- epilogue ----
#pragma unroll
  for (int i = 0; i < 4; i++) {
    const int q = qg * 4 + i;
    float invl = 1.f / Ls[q];
    float* op = g_ctx + ((size_t)(b * TT + q0 + q)) * (NH * HD) + h * HD;
    float4 o0 = acc[i][0], o1 = acc[i][1];
    o0.x *= invl; o0.y *= invl; o0.z *= invl; o0.w *= invl;
    o1.x *= invl; o1.y *= invl; o1.z *= invl; o1.w *= invl;
    *(float4*)(op + dg2 * 4) = o0;
    *(float4*)(op + 64 + dg2 * 4) = o1;
  }
}

// ---------------- launch ------------------------------------------------------
extern "C" void kernel_launch(void* const* d_in, const int* in_sizes, int n_in,
                              void* d_out, int out_size) {
  const float* x = (const float*)d_in[0];
  const float* cosT = (const float*)d_in[2];
  const float* sinT = (const float*)d_in[3];
  const float* prev_k = (const float*)d_in[5];
  const float* prev_v = (const float*)d_in[6];
  const float* Wq = (const float*)d_in[7];
  const float* Wk = (const float*)d_in[8];
  const float* Wv = (const float*)d_in[9];
  const float* Wo = (const float*)d_in[10];
  const float* qw = (const float*)d_in[11];
  const float* kw = (const float*)d_in[12];

  float* out = (float*)d_out;
  const size_t out_elems = (size_t)BB * TT * DIN;
  const size_t kv_elems = (size_t)BB * HKV * LFULL * HD;

  float* fullk;
  float* fullv;
  if ((size_t)out_size >= out_elems + 2 * kv_elems) {
    fullk = out + out_elems;
    fullv = fullk + kv_elems;
  } else {
    cudaGetSymbolAddress((void**)&fullk, g_fk);
    cudaGetSymbolAddress((void**)&fullv, g_fv);
  }

  float *qraw, *kraw, *vraw, *ctx;
  cudaGetSymbolAddress((void**)&qraw, g_qraw);
  cudaGetSymbolAddress((void**)&kraw, g_kraw);
  cudaGetSymbolAddress((void**)&vraw, g_vraw);
  cudaGetSymbolAddress((void**)&ctx, g_ctx);

  const int M = BB * TT;  // 2048

  sgemm_nt<<<dim3((NH * HD) / 128, M / 128), 256>>>(x, Wq, qraw, M, NH * HD, DIN);
  sgemm_nt<<<dim3((HKV * HD) / 128, M / 128), 256>>>(x, Wk, kraw, M, HKV * HD, DIN);
  sgemm_nt<<<dim3((HKV * HD) / 128, M / 128), 256>>>(x, Wv, vraw, M, HKV * HD, DIN);

  copy_prev<<<2048, 256>>>((const float4*)prev_k, (const float4*)prev_v,
                           (float4*)fullk, (float4*)fullv);

  norm_rope_kernel<<<dim3(BB * TT, NH + 2 * HKV), 128>>>(cosT, sinT, qw, kw, fullk, fullv);

  const int ATTN_SMEM = (TQ * DP + 2 * SK * DP + TQ * PP) * 16 + 3 * TQ * 4;  // ~119.5KB
  cudaFuncSetAttribute(attn_kernel, cudaFuncAttributeMaxDynamicSharedMemorySize, ATTN_SMEM);
  attn_kernel<<<BB * NH * (TT / TQ), 256, ATTN_SMEM>>>(fullk, fullv);

  sgemm_nt<<<dim3(DIN / 128, M / 128), 256>>>(ctx, Wo, out, M, DIN, NH * HD);
}

// round 7
// speedup vs baseline: 1.9998x; 1.3276x over previous
#include <cuda_runtime.h>
#include <cuda_bf16.h>
#include <math.h>
#include <cstdint>

#define BB 2
#define TT 1024
#define DIN 2048
#define NH 32
#define HKV 8
#define HD 128
#define LPREV 1024
#define LFULL 2048

// ---------------- scratch ----------------------------------------------------
__device__ float g_qraw[(size_t)BB * TT * NH * HD];
__device__ float g_kraw[(size_t)BB * TT * HKV * HD];
__device__ float g_vraw[(size_t)BB * TT * HKV * HD];
__device__ float g_qh[(size_t)BB * NH * TT * HD];
__device__ float g_ctx[(size_t)BB * TT * NH * HD];
__device__ float g_fk[(size_t)BB * HKV * LFULL * HD];
__device__ float g_fv[(size_t)BB * HKV * LFULL * HD];

// ---------------- mma.sync GEMM: C[M,N] = A[M,K] * W[N,K]^T ------------------
// bf16 hi/lo 3-term split for fp32-grade accuracy. 128x128 CTA tile.
// 8 warps: warp-rows (wid>>1)*32, warp-cols (wid&1)*64.
// smem per buffer (40960 B): Ahi[128x(32+8)bf16=80B rows], Alo, Bhi, Blo.
#define KS 32          // K per stage
#define RSB 80         // row stride bytes (32 bf16 data + 8 pad)
#define MATB 10240     // bytes per matrix (128 * 80)
#define BUFB 40960     // bytes per buffer (4 matrices)
#define GEMM_SMEM (2 * BUFB)

__device__ __forceinline__ void mma_bf16(float* c, uint32_t a0, uint32_t a1,
                                         uint32_t a2, uint32_t a3,
                                         uint32_t b0, uint32_t b1) {
  asm volatile(
      "mma.sync.aligned.m16n8k16.row.col.f32.bf16.bf16.f32 "
      "{%0,%1,%2,%3}, {%4,%5,%6,%7}, {%8,%9}, {%0,%1,%2,%3};"
      : "+f"(c[0]), "+f"(c[1]), "+f"(c[2]), "+f"(c[3])
      : "r"(a0), "r"(a1), "r"(a2), "r"(a3), "r"(b0), "r"(b1));
}

__device__ __forceinline__ void stage_load(const float* __restrict__ A,
                                           const float* __restrict__ W,
                                           char* sm, int m0, int n0, int K,
                                           int k0, int buf, int tid) {
  char* base = sm + buf * BUFB;
#pragma unroll
  for (int i = 0; i < 4; i++) {
    int c = tid + i * 256;      // 0..1023
    int mat = c >> 9;           // 0 = A, 1 = B(W)
    int idx = c & 511;
    int row = idx >> 2;         // 0..127
    int kc = idx & 3;           // 8-float chunk
    const float* gp = (mat ? W + (size_t)(n0 + row) * K
                           : A + (size_t)(m0 + row) * K) + k0 + kc * 8;
    float4 f0 = *(const float4*)gp;
    float4 f1 = *(const float4*)(gp + 4);
    float v[8] = {f0.x, f0.y, f0.z, f0.w, f1.x, f1.y, f1.z, f1.w};
    union { __nv_bfloat162 h2[4]; float4 f4; } hi, lo;
#pragma unroll
    for (int j = 0; j < 4; j++) {
      float a0 = v[2 * j], a1 = v[2 * j + 1];
      __nv_bfloat16 h0 = __float2bfloat16(a0);
      __nv_bfloat16 h1 = __float2bfloat16(a1);
      hi.h2[j] = __nv_bfloat162(h0, h1);
      lo.h2[j] = __floats2bfloat162_rn(a0 - __bfloat162float(h0),
                                       a1 - __bfloat162float(h1));
    }
    char* mb = base + mat * (2 * MATB) + row * RSB + kc * 16;
    *(float4*)mb = hi.f4;               // hi matrix
    *(float4*)(mb + MATB) = lo.f4;      // lo matrix
  }
}

__global__ __launch_bounds__(256) void gemm_mma(const float* __restrict__ A,
                                                const float* __restrict__ W,
                                                float* __restrict__ C,
                                                int M, int N, int K) {
  extern __shared__ char sm[];
  const int tid = threadIdx.x;
  const int wid = tid >> 5, lane = tid & 31;
  const int m0 = blockIdx.y * 128, n0 = blockIdx.x * 128;
  const int wr = wid >> 1, wc = wid & 1;   // warp row (0..3), warp col (0..1)
  const int g = lane >> 2, q = lane & 3;

  float acc[2][8][4];
#pragma unroll
  for (int mi = 0; mi < 2; mi++)
#pragma unroll
    for (int ni = 0; ni < 8; ni++)
#pragma unroll
      for (int r = 0; r < 4; r++) acc[mi][ni][r] = 0.f;

  stage_load(A, W, sm, m0, n0, K, 0, 0, tid);
  __syncthreads();

  const int nstage = K >> 5;
  for (int s = 0; s < nstage; s++) {
    if (s + 1 < nstage)
      stage_load(A, W, sm, m0, n0, K, (s + 1) << 5, (s + 1) & 1, tid);

    char* bufb = sm + (s & 1) * BUFB;
#pragma unroll
    for (int ks = 0; ks < 2; ks++) {
      const int kb = ks * 32 + q * 4;  // byte offset of this thread's k-pair
      uint32_t ah[2][4], al[2][4];
#pragma unroll
      for (int mi = 0; mi < 2; mi++) {
        const char* ra = bufb + (wr * 32 + mi * 16 + g) * RSB + kb;
        ah[mi][0] = *(const uint32_t*)(ra);
        ah[mi][1] = *(const uint32_t*)(ra + 8 * RSB);
        ah[mi][2] = *(const uint32_t*)(ra + 16);
        ah[mi][3] = *(const uint32_t*)(ra + 8 * RSB + 16);
        al[mi][0] = *(const uint32_t*)(ra + MATB);
        al[mi][1] = *(const uint32_t*)(ra + MATB + 8 * RSB);
        al[mi][2] = *(const uint32_t*)(ra + MATB + 16);
        al[mi][3] = *(const uint32_t*)(ra + MATB + 8 * RSB + 16);
      }
#pragma unroll
      for (int ni = 0; ni < 8; ni++) {
        const char* rb = bufb + 2 * MATB + (wc * 64 + ni * 8 + g) * RSB + kb;
        uint32_t bh0 = *(const uint32_t*)(rb);
        uint32_t bh1 = *(const uint32_t*)(rb + 16);
        uint32_t bl0 = *(const uint32_t*)(rb + MATB);
        uint32_t bl1 = *(const uint32_t*)(rb + MATB + 16);
#pragma unroll
        for (int mi = 0; mi < 2; mi++) {
          mma_bf16(acc[mi][ni], ah[mi][0], ah[mi][1], ah[mi][2], ah[mi][3], bh0, bh1);
          mma_bf16(acc[mi][ni], al[mi][0], al[mi][1], al[mi][2], al[mi][3], bh0, bh1);
          mma_bf16(acc[mi][ni], ah[mi][0], ah[mi][1], ah[mi][2], ah[mi][3], bl0, bl1);
        }
      }
    }
    __syncthreads();
  }

  // epilogue: c0,c1 -> (row g, cols 2q,2q+1); c2,c3 -> row g+8
#pragma unroll
  for (int mi = 0; mi < 2; mi++) {
    const int r = m0 + wr * 32 + mi * 16 + g;
#pragma unroll
    for (int ni = 0; ni < 8; ni++) {
      const int c0 = n0 + wc * 64 + ni * 8 + q * 2;
      *(float2*)(C + (size_t)r * N + c0) = make_float2(acc[mi][ni][0], acc[mi][ni][1]);
      *(float2*)(C + (size_t)(r + 8) * N + c0) = make_float2(acc[mi][ni][2], acc[mi][ni][3]);
    }
  }
}

// ---------------- copy prev_k/prev_v -----------------------------------------
__global__ void copy_prev(const float4* __restrict__ pk, const float4* __restrict__ pv,
                          float4* __restrict__ fk, float4* __restrict__ fv) {
  int i = blockIdx.x * blockDim.x + threadIdx.x;
  const int total = BB * HKV * LPREV * HD / 4;
  if (i >= total) return;
  const int per = LPREV * HD / 4;
  const int dper = LFULL * HD / 4;
  int bh = i / per, off = i - bh * per;
  fk[(size_t)bh * dper + off] = pk[i];
  fv[(size_t)bh * dper + off] = pv[i];
}

// ---------------- RMSNorm + RoPE + scatter -----------------------------------
__global__ void norm_rope_kernel(const float* __restrict__ cosT,
                                 const float* __restrict__ sinT,
                                 const float* __restrict__ qw,
                                 const float* __restrict__ kw,
                                 float* __restrict__ fullk,
                                 float* __restrict__ fullv) {
  int bt = blockIdx.x;
  int b = bt >> 10, t = bt & 1023;
  int role = blockIdx.y;
  int d = threadIdx.x;
  __shared__ float red[128];
  __shared__ float row[128];
  int pos = LPREV + t;

  if (role < NH) {
    int h = role;
    float v = g_qraw[(size_t)bt * (NH * HD) + h * HD + d];
    red[d] = v * v;
    __syncthreads();
#pragma unroll
    for (int s = 64; s > 0; s >>= 1) {
      if (d < s) red[d] += red[d + s];
      __syncthreads();
    }
    float inv = rsqrtf(red[0] * (1.0f / HD) + 1e-6f);
    float xn = v * inv * qw[d];
    row[d] = xn;
    __syncthreads();
    float rot = (d < 64) ? -row[d + 64] : row[d - 64];
    float o = xn * cosT[pos * HD + d] + rot * sinT[pos * HD + d];
    g_qh[(((size_t)b * NH + h) * TT + t) * HD + d] = o;
  } else if (role < NH + HKV) {
    int h = role - NH;
    float v = g_kraw[(size_t)bt * (HKV * HD) + h * HD + d];
    red[d] = v * v;
    __syncthreads();
#pragma unroll
    for (int s = 64; s > 0; s >>= 1) {
      if (d < s) red[d] += red[d + s];
      __syncthreads();
    }
    float inv = rsqrtf(red[0] * (1.0f / HD) + 1e-6f);
    float xn = v * inv * kw[d];
    row[d] = xn;
    __syncthreads();
    float rot = (d < 64) ? -row[d + 64] : row[d - 64];
    float o = xn * cosT[pos * HD + d] + rot * sinT[pos * HD + d];
    fullk[(((size_t)b * HKV + h) * LFULL + LPREV + t) * HD + d] = o;
  } else {
    int h = role - NH - HKV;
    fullv[(((size_t)b * HKV + h) * LFULL + LPREV + t) * HD + d] =
        g_vraw[(size_t)bt * (HKV * HD) + h * HD + d];
  }
}

// ---------------- flash attention v2 (register-blocked, fp32) ----------------
#define TQ 64
#define SK 64
#define DP 33
#define PP 17

__global__ __launch_bounds__(256, 1) void attn_kernel(const float* __restrict__ fullk,
                                                      const float* __restrict__ fullv) {
  extern __shared__ float smemf[];
  float4* Qs = (float4*)smemf;
  float4* Ks = Qs + TQ * DP;
  float4* Vs = Ks + SK * DP;
  float4* Ps = Vs + SK * DP;
  float* Pf = (float*)Ps;
  float* Ms = (float*)(Ps + TQ * PP);
  float* Ls = Ms + TQ;
  float* Cs = Ls + TQ;

  const int tid = threadIdx.x;
  const int bx = blockIdx.x;
  const int qt = bx & 15, h = (bx >> 4) & 31, b = bx >> 9;
  const int q0 = qt * TQ;
  const int kg = tid & 15;
  const int qg = tid >> 4;
  const int dg2 = tid & 15;

  const float scale = 0.08838834764831845f;

  const float4* qgp = (const float4*)(g_qh + (((size_t)b * NH + h) * TT + q0) * HD);
  for (int i = tid; i < TQ * 32; i += 256) {
    int r = i >> 5, c = i & 31;
    float4 v = qgp[r * 32 + c];
    v.x *= scale; v.y *= scale; v.z *= scale; v.w *= scale;
    Qs[r * DP + c] = v;
  }
  if (tid < TQ) { Ms[tid] = -1e30f; Ls[tid] = 0.f; }

  const float4* kgp = (const float4*)(fullk + (((size_t)b * HKV + (h >> 2)) * LFULL) * HD);
  const float4* vgp = (const float4*)(fullv + (((size_t)b * HKV + (h >> 2)) * LFULL) * HD);

  float4 acc[4][2];
#pragma unroll
  for (int i = 0; i < 4; i++) {
    acc[i][0] = make_float4(0.f, 0.f, 0.f, 0.f);
    acc[i][1] = make_float4(0.f, 0.f, 0.f, 0.f);
  }

  const int diag = LPREV + q0;
  const int ntiles = (diag + TQ) / SK;

  for (int jt = 0; jt < ntiles; jt++) {
    const int j0 = jt * SK;
    __syncthreads();
    for (int i = tid; i < SK * 32; i += 256) {
      int r = i >> 5, c = i & 31;
      Ks[r * DP + c] = kgp[(size_t)(j0 + r) * 32 + c];
      Vs[r * DP + c] = vgp[(size_t)(j0 + r) * 32 + c];
    }
    __syncthreads();

    float s[4][4];
#pragma unroll
    for (int i = 0; i < 4; i++)
#pragma unroll
      for (int j = 0; j < 4; j++) s[i][j] = 0.f;

#pragma unroll 4
    for (int c = 0; c < 32; c++) {
      float4 qv[4], kv[4];
#pragma unroll
      for (int i = 0; i < 4; i++) qv[i] = Qs[(qg * 4 + i) * DP + c];
#pragma unroll
      for (int j = 0; j < 4; j++) kv[j] = Ks[(kg + 16 * j) * DP + c];
#pragma unroll
      for (int i = 0; i < 4; i++)
#pragma unroll
        for (int j = 0; j < 4; j++)
          s[i][j] += qv[i].x * kv[j].x + qv[i].y * kv[j].y +
                     qv[i].z * kv[j].z + qv[i].w * kv[j].w;
    }

    if (j0 == diag) {
#pragma unroll
      for (int i = 0; i < 4; i++)
#pragma unroll
        for (int j = 0; j < 4; j++)
          if (kg + 16 * j > qg * 4 + i) s[i][j] = -1e30f;
    }

#pragma unroll
    for (int i = 0; i < 4; i++) {
      const int q = qg * 4 + i;
      float rmax = fmaxf(fmaxf(s[i][0], s[i][1]), fmaxf(s[i][2], s[i][3]));
      rmax = fmaxf(rmax, __shfl_xor_sync(0xffffffffu, rmax, 1));
      rmax = fmaxf(rmax, __shfl_xor_sync(0xffffffffu, rmax, 2));
      rmax = fmaxf(rmax, __shfl_xor_sync(0xffffffffu, rmax, 4));
      rmax = fmaxf(rmax, __shfl_xor_sync(0xffffffffu, rmax, 8));
      float mo = Ms[q];
      float nm = fmaxf(mo, rmax);
      float psum = 0.f;
#pragma unroll
      for (int j = 0; j < 4; j++) {
        float p = __expf(s[i][j] - nm);
        psum += p;
        Pf[q * (PP * 4) + kg + 16 * j] = p;
      }
      psum += __shfl_xor_sync(0xffffffffu, psum, 1);
      psum += __shfl_xor_sync(0xffffffffu, psum, 2);
      psum += __shfl_xor_sync(0xffffffffu, psum, 4);
      psum += __shfl_xor_sync(0xffffffffu, psum, 8);
      if (kg == 0) {
        float corr = __expf(mo - nm);
        Cs[q] = corr;
        Ls[q] = Ls[q] * corr + psum;
        Ms[q] = nm;
      }
    }
    __syncthreads();

    float corr[4];
#pragma unroll
    for (int i = 0; i < 4; i++) corr[i] = Cs[qg * 4 + i];
#pragma unroll
    for (int i = 0; i < 4; i++) {
      acc[i][0].x *= corr[i]; acc[i][0].y *= corr[i];
      acc[i][0].z *= corr[i]; acc[i][0].w *= corr[i];
      acc[i][1].x *= corr[i]; acc[i][1].y *= corr[i];
      acc[i][1].z *= corr[i]; acc[i][1].w *= corr[i];
    }
#pragma unroll 4
    for (int kc = 0; kc < 16; kc++) {
      float4 p4[4];
#pragma unroll
      for (int i = 0; i < 4; i++) p4[i] = Ps[(qg * 4 + i) * PP + kc];
#pragma unroll
      for (int kk = 0; kk < 4; kk++) {
        float4 v0 = Vs[(kc * 4 + kk) * DP + dg2];
        float4 v1 = Vs[(kc * 4 + kk) * DP + dg2 + 16];
#pragma unroll
        for (int i = 0; i < 4; i++) {
          float p = ((const float*)&p4[i])[kk];
          acc[i][0].x += p * v0.x; acc[i][0].y += p * v0.y;
          acc[i][0].z += p * v0.z; acc[i][0].w += p * v0.w;
          acc[i][1].x += p * v1.x; acc[i][1].y += p * v1.y;
          acc[i][1].z += p * v1.z; acc[i][1].w += p * v1.w;
        }
      }
    }
  }

#pragma unroll
  for (int i = 0; i < 4; i++) {
    const int q = qg * 4 + i;
    float invl = 1.f / Ls[q];
    float* op = g_ctx + ((size_t)(b * TT + q0 + q)) * (NH * HD) + h * HD;
    float4 o0 = acc[i][0], o1 = acc[i][1];
    o0.x *= invl; o0.y *= invl; o0.z *= invl; o0.w *= invl;
    o1.x *= invl; o1.y *= invl; o1.z *= invl; o1.w *= invl;
    *(float4*)(op + dg2 * 4) = o0;
    *(float4*)(op + 64 + dg2 * 4) = o1;
  }
}

// ---------------- launch ------------------------------------------------------
extern "C" void kernel_launch(void* const* d_in, const int* in_sizes, int n_in,
                              void* d_out, int out_size) {
  const float* x = (const float*)d_in[0];
  const float* cosT = (const float*)d_in[2];
  const float* sinT = (const float*)d_in[3];
  const float* prev_k = (const float*)d_in[5];
  const float* prev_v = (const float*)d_in[6];
  const float* Wq = (const float*)d_in[7];
  const float* Wk = (const float*)d_in[8];
  const float* Wv = (const float*)d_in[9];
  const float* Wo = (const float*)d_in[10];
  const float* qw = (const float*)d_in[11];
  const float* kw = (const float*)d_in[12];

  float* out = (float*)d_out;
  const size_t out_elems = (size_t)BB * TT * DIN;
  const size_t kv_elems = (size_t)BB * HKV * LFULL * HD;

  float* fullk;
  float* fullv;
  if ((size_t)out_size >= out_elems + 2 * kv_elems) {
    fullk = out + out_elems;
    fullv = fullk + kv_elems;
  } else {
    cudaGetSymbolAddress((void**)&fullk, g_fk);
    cudaGetSymbolAddress((void**)&fullv, g_fv);
  }

  float *qraw, *kraw, *vraw, *ctx;
  cudaGetSymbolAddress((void**)&qraw, g_qraw);
  cudaGetSymbolAddress((void**)&kraw, g_kraw);
  cudaGetSymbolAddress((void**)&vraw, g_vraw);
  cudaGetSymbolAddress((void**)&ctx, g_ctx);

  const int M = BB * TT;  // 2048

  cudaFuncSetAttribute(gemm_mma, cudaFuncAttributeMaxDynamicSharedMemorySize, GEMM_SMEM);

  gemm_mma<<<dim3((NH * HD) / 128, M / 128), 256, GEMM_SMEM>>>(x, Wq, qraw, M, NH * HD, DIN);
  gemm_mma<<<dim3((HKV * HD) / 128, M / 128), 256, GEMM_SMEM>>>(x, Wk, kraw, M, HKV * HD, DIN);
  gemm_mma<<<dim3((HKV * HD) / 128, M / 128), 256, GEMM_SMEM>>>(x, Wv, vraw, M, HKV * HD, DIN);

  copy_prev<<<2048, 256>>>((const float4*)prev_k, (const float4*)prev_v,
                           (float4*)fullk, (float4*)fullv);

  norm_rope_kernel<<<dim3(BB * TT, NH + 2 * HKV), 128>>>(cosT, sinT, qw, kw, fullk, fullv);

  const int ATTN_SMEM = (TQ * DP + 2 * SK * DP + TQ * PP) * 16 + 3 * TQ * 4;
  cudaFuncSetAttribute(attn_kernel, cudaFuncAttributeMaxDynamicSharedMemorySize, ATTN_SMEM);
  attn_kernel<<<BB * NH * (TT / TQ), 256, ATTN_SMEM>>>(fullk, fullv);

  gemm_mma<<<dim3(DIN / 128, M / 128), 256, GEMM_SMEM>>>(ctx, Wo, out, M, DIN, NH * HD);
}

// round 9
// speedup vs baseline: 3.1966x; 1.5985x over previous
#include <cuda_runtime.h>
#include <cuda_bf16.h>
#include <math.h>
#include <cstdint>

#define BB 2
#define TT 1024
#define DIN 2048
#define NH 32
#define HKV 8
#define HD 128
#define LPREV 1024
#define LFULL 2048

// ---------------- scratch ----------------------------------------------------
__device__ float g_qraw[(size_t)BB * TT * NH * HD];
__device__ float g_kraw[(size_t)BB * TT * HKV * HD];
__device__ float g_vraw[(size_t)BB * TT * HKV * HD];
__device__ float g_ctx[(size_t)BB * TT * NH * HD];
__device__ float g_fk[(size_t)BB * HKV * LFULL * HD];
__device__ float g_fv[(size_t)BB * HKV * LFULL * HD];
// bf16 hi/lo operand copies for tensor-core attention
__device__ __nv_bfloat16 g_qhi[(size_t)BB * NH * TT * HD];
__device__ __nv_bfloat16 g_qlo[(size_t)BB * NH * TT * HD];
__device__ __nv_bfloat16 g_khi[(size_t)BB * HKV * LFULL * HD];
__device__ __nv_bfloat16 g_klo[(size_t)BB * HKV * LFULL * HD];
__device__ __nv_bfloat16 g_vthi[(size_t)BB * HKV * HD * LFULL];  // [bh][d][key]
__device__ __nv_bfloat16 g_vtlo[(size_t)BB * HKV * HD * LFULL];

// ---------------- mma helper --------------------------------------------------
__device__ __forceinline__ void mma_bf16(float* c, uint32_t a0, uint32_t a1,
                                         uint32_t a2, uint32_t a3,
                                         uint32_t b0, uint32_t b1) {
  asm volatile(
      "mma.sync.aligned.m16n8k16.row.col.f32.bf16.bf16.f32 "
      "{%0,%1,%2,%3}, {%4,%5,%6,%7}, {%8,%9}, {%0,%1,%2,%3};"
      : "+f"(c[0]), "+f"(c[1]), "+f"(c[2]), "+f"(c[3])
      : "r"(a0), "r"(a1), "r"(a2), "r"(a3), "r"(b0), "r"(b1));
}

__device__ __forceinline__ uint32_t pack_bf2(float a, float b) {
  __nv_bfloat162 t = __floats2bfloat162_rn(a, b);
  return *(uint32_t*)&t;
}

// ---------------- mma.sync GEMM: C[M,N] = A[M,K] * W[N,K]^T ------------------
#define RSB 80
#define MATB 10240
#define BUFB 40960
#define GEMM_SMEM (2 * BUFB)

__device__ __forceinline__ void stage_load(const float* __restrict__ A,
                                           const float* __restrict__ W,
                                           char* sm, int m0, int n0, int K,
                                           int k0, int buf, int tid) {
  char* base = sm + buf * BUFB;
#pragma unroll
  for (int i = 0; i < 4; i++) {
    int c = tid + i * 256;
    int mat = c >> 9;
    int idx = c & 511;
    int row = idx >> 2;
    int kc = idx & 3;
    const float* gp = (mat ? W + (size_t)(n0 + row) * K
                           : A + (size_t)(m0 + row) * K) + k0 + kc * 8;
    float4 f0 = *(const float4*)gp;
    float4 f1 = *(const float4*)(gp + 4);
    float v[8] = {f0.x, f0.y, f0.z, f0.w, f1.x, f1.y, f1.z, f1.w};
    union { __nv_bfloat162 h2[4]; float4 f4; } hi, lo;
#pragma unroll
    for (int j = 0; j < 4; j++) {
      float a0 = v[2 * j], a1 = v[2 * j + 1];
      __nv_bfloat16 h0 = __float2bfloat16(a0);
      __nv_bfloat16 h1 = __float2bfloat16(a1);
      hi.h2[j] = __nv_bfloat162(h0, h1);
      lo.h2[j] = __floats2bfloat162_rn(a0 - __bfloat162float(h0),
                                       a1 - __bfloat162float(h1));
    }
    char* mb = base + mat * (2 * MATB) + row * RSB + kc * 16;
    *(float4*)mb = hi.f4;
    *(float4*)(mb + MATB) = lo.f4;
  }
}

__global__ __launch_bounds__(256) void gemm_mma(const float* __restrict__ A,
                                                const float* __restrict__ W,
                                                float* __restrict__ C,
                                                int M, int N, int K) {
  extern __shared__ char sm[];
  const int tid = threadIdx.x;
  const int wid = tid >> 5, lane = tid & 31;
  const int m0 = blockIdx.y * 128, n0 = blockIdx.x * 128;
  const int wr = wid >> 1, wc = wid & 1;
  const int g = lane >> 2, q = lane & 3;

  float acc[2][8][4];
#pragma unroll
  for (int mi = 0; mi < 2; mi++)
#pragma unroll
    for (int ni = 0; ni < 8; ni++)
#pragma unroll
      for (int r = 0; r < 4; r++) acc[mi][ni][r] = 0.f;

  stage_load(A, W, sm, m0, n0, K, 0, 0, tid);
  __syncthreads();

  const int nstage = K >> 5;
  for (int s = 0; s < nstage; s++) {
    if (s + 1 < nstage)
      stage_load(A, W, sm, m0, n0, K, (s + 1) << 5, (s + 1) & 1, tid);

    char* bufb = sm + (s & 1) * BUFB;
#pragma unroll
    for (int ks = 0; ks < 2; ks++) {
      const int kb = ks * 32 + q * 4;
      uint32_t ah[2][4], al[2][4];
#pragma unroll
      for (int mi = 0; mi < 2; mi++) {
        const char* ra = bufb + (wr * 32 + mi * 16 + g) * RSB + kb;
        ah[mi][0] = *(const uint32_t*)(ra);
        ah[mi][1] = *(const uint32_t*)(ra + 8 * RSB);
        ah[mi][2] = *(const uint32_t*)(ra + 16);
        ah[mi][3] = *(const uint32_t*)(ra + 8 * RSB + 16);
        al[mi][0] = *(const uint32_t*)(ra + MATB);
        al[mi][1] = *(const uint32_t*)(ra + MATB + 8 * RSB);
        al[mi][2] = *(const uint32_t*)(ra + MATB + 16);
        al[mi][3] = *(const uint32_t*)(ra + MATB + 8 * RSB + 16);
      }
#pragma unroll
      for (int ni = 0; ni < 8; ni++) {
        const char* rb = bufb + 2 * MATB + (wc * 64 + ni * 8 + g) * RSB + kb;
        uint32_t bh0 = *(const uint32_t*)(rb);
        uint32_t bh1 = *(const uint32_t*)(rb + 16);
        uint32_t bl0 = *(const uint32_t*)(rb + MATB);
        uint32_t bl1 = *(const uint32_t*)(rb + MATB + 16);
#pragma unroll
        for (int mi = 0; mi < 2; mi++) {
          mma_bf16(acc[mi][ni], ah[mi][0], ah[mi][1], ah[mi][2], ah[mi][3], bh0, bh1);
          mma_bf16(acc[mi][ni], al[mi][0], al[mi][1], al[mi][2], al[mi][3], bh0, bh1);
          mma_bf16(acc[mi][ni], ah[mi][0], ah[mi][1], ah[mi][2], ah[mi][3], bl0, bl1);
        }
      }
    }
    __syncthreads();
  }

#pragma unroll
  for (int mi = 0; mi < 2; mi++) {
    const int r = m0 + wr * 32 + mi * 16 + g;
#pragma unroll
    for (int ni = 0; ni < 8; ni++) {
      const int c0 = n0 + wc * 64 + ni * 8 + q * 2;
      *(float2*)(C + (size_t)r * N + c0) = make_float2(acc[mi][ni][0], acc[mi][ni][1]);
      *(float2*)(C + (size_t)(r + 8) * N + c0) = make_float2(acc[mi][ni][2], acc[mi][ni][3]);
    }
  }
}

// ---------------- copy prev_k/prev_v + K bf16 split ---------------------------
__global__ void copy_prev(const float4* __restrict__ pk, const float4* __restrict__ pv,
                          float4* __restrict__ fk, float4* __restrict__ fv,
                          __nv_bfloat16* __restrict__ khi, __nv_bfloat16* __restrict__ klo) {
  int i = blockIdx.x * blockDim.x + threadIdx.x;
  const int total = BB * HKV * LPREV * HD / 4;
  if (i >= total) return;
  const int per = LPREV * HD / 4;
  const int dper = LFULL * HD / 4;
  int bh = i / per, off = i - bh * per;
  float4 kv = pk[i];
  fk[(size_t)bh * dper + off] = kv;
  fv[(size_t)bh * dper + off] = pv[i];
  float v[4] = {kv.x, kv.y, kv.z, kv.w};
  union { __nv_bfloat16 h[4]; uint2 u; } H, L;
#pragma unroll
  for (int j = 0; j < 4; j++) {
    H.h[j] = __float2bfloat16(v[j]);
    L.h[j] = __float2bfloat16(v[j] - __bfloat162float(H.h[j]));
  }
  size_t kb = (size_t)bh * LFULL * HD + (size_t)off * 4;
  *(uint2*)(khi + kb) = H.u;
  *(uint2*)(klo + kb) = L.u;
}

// ---------------- RMSNorm + RoPE + scatter (+ bf16 splits) --------------------
__global__ void norm_rope_kernel(const float* __restrict__ cosT,
                                 const float* __restrict__ sinT,
                                 const float* __restrict__ qw,
                                 const float* __restrict__ kw,
                                 float* __restrict__ fullk,
                                 float* __restrict__ fullv,
                                 __nv_bfloat16* __restrict__ qhi,
                                 __nv_bfloat16* __restrict__ qlo,
                                 __nv_bfloat16* __restrict__ khi,
                                 __nv_bfloat16* __restrict__ klo) {
  int bt = blockIdx.x;
  int b = bt >> 10, t = bt & 1023;
  int role = blockIdx.y;
  int d = threadIdx.x;
  __shared__ float red[128];
  __shared__ float row[128];
  int pos = LPREV + t;
  const float scale = 0.08838834764831845f;  // 1/sqrt(128)

  if (role < NH) {
    int h = role;
    float v = g_qraw[(size_t)bt * (NH * HD) + h * HD + d];
    red[d] = v * v;
    __syncthreads();
#pragma unroll
    for (int s = 64; s > 0; s >>= 1) {
      if (d < s) red[d] += red[d + s];
      __syncthreads();
    }
    float inv = rsqrtf(red[0] * (1.0f / HD) + 1e-6f);
    float xn = v * inv * qw[d];
    row[d] = xn;
    __syncthreads();
    float rot = (d < 64) ? -row[d + 64] : row[d - 64];
    float o = (xn * cosT[pos * HD + d] + rot * sinT[pos * HD + d]) * scale;
    __nv_bfloat16 hh = __float2bfloat16(o);
    size_t qi = (((size_t)b * NH + h) * TT + t) * HD + d;
    qhi[qi] = hh;
    qlo[qi] = __float2bfloat16(o - __bfloat162float(hh));
  } else if (role < NH + HKV) {
    int h = role - NH;
    float v = g_kraw[(size_t)bt * (HKV * HD) + h * HD + d];
    red[d] = v * v;
    __syncthreads();
#pragma unroll
    for (int s = 64; s > 0; s >>= 1) {
      if (d < s) red[d] += red[d + s];
      __syncthreads();
    }
    float inv = rsqrtf(red[0] * (1.0f / HD) + 1e-6f);
    float xn = v * inv * kw[d];
    row[d] = xn;
    __syncthreads();
    float rot = (d < 64) ? -row[d + 64] : row[d - 64];
    float o = xn * cosT[pos * HD + d] + rot * sinT[pos * HD + d];
    size_t ki = (((size_t)b * HKV + h) * LFULL + LPREV + t) * HD + d;
    fullk[ki] = o;
    __nv_bfloat16 hh = __float2bfloat16(o);
    khi[ki] = hh;
    klo[ki] = __float2bfloat16(o - __bfloat162float(hh));
  } else {
    int h = role - NH - HKV;
    fullv[(((size_t)b * HKV + h) * LFULL + LPREV + t) * HD + d] =
        g_vraw[(size_t)bt * (HKV * HD) + h * HD + d];
  }
}

// ---------------- V transpose + bf16 split: fullv -> [bh][d][key] -------------
__global__ void conv_vt(const float* __restrict__ fv,
                        __nv_bfloat16* __restrict__ vthi,
                        __nv_bfloat16* __restrict__ vtlo) {
  __shared__ float tbuf[32][33];
  int bh = blockIdx.z;
  int k0 = blockIdx.x * 32, d0 = blockIdx.y * 32;
  int tx = threadIdx.x, ty = threadIdx.y;  // 32 x 8
#pragma unroll
  for (int i = 0; i < 4; i++)
    tbuf[ty + 8 * i][tx] = fv[((size_t)bh * LFULL + k0 + ty + 8 * i) * HD + d0 + tx];
  __syncthreads();
#pragma unroll
  for (int i = 0; i < 4; i++) {
    float v = tbuf[tx][ty + 8 * i];
    __nv_bfloat16 hh = __float2bfloat16(v);
    size_t oi = ((size_t)bh * HD + d0 + ty + 8 * i) * LFULL + k0 + tx;
    vthi[oi] = hh;
    vtlo[oi] = __float2bfloat16(v - __bfloat162float(hh));
  }
}

// ---------------- tensor-core flash attention ---------------------------------
// CTA: 256 thr, 128 q-rows, 64-key tiles, bf16 hi/lo 3-term splits.
#define AQ 128
#define KPB 272                       // K smem row pitch (128 bf16 + pad)
#define VPB 144                       // VT smem row pitch (64 bf16 + pad)
#define KMAT (64 * KPB)               // 17408
#define VMAT (128 * VPB)              // 18432
#define ABUF (2 * KMAT + 2 * VMAT)    // 71680
#define ATTN_SMEM (2 * ABUF)          // 143360

__device__ __forceinline__ void attn_stage(char* sm, int buf,
                                           const __nv_bfloat16* khi,
                                           const __nv_bfloat16* klo,
                                           const __nv_bfloat16* vthi,
                                           const __nv_bfloat16* vtlo,
                                           size_t bhk, int j0, int tid) {
  char* base = sm + buf * ABUF;
#pragma unroll
  for (int i = 0; i < 16; i++) {
    int idx = tid + i * 256;
    int mat = idx >> 10;
    int x = idx & 1023;
    if (mat < 2) {
      int row = x >> 4, c = x & 15;
      const __nv_bfloat16* src = (mat ? klo : khi) + (bhk * LFULL + j0 + row) * HD + c * 8;
      char* dst = base + mat * KMAT + row * KPB + c * 16;
      *(float4*)dst = *(const float4*)src;
    } else {
      int row = x >> 3, c = x & 7;
      const __nv_bfloat16* src = (mat == 3 ? vtlo : vthi) + (bhk * HD + row) * LFULL + j0 + c * 8;
      char* dst = base + 2 * KMAT + (mat - 2) * VMAT + row * VPB + c * 16;
      *(float4*)dst = *(const float4*)src;
    }
  }
}

__global__ __launch_bounds__(256, 1) void attn_mma(
    const __nv_bfloat16* __restrict__ qhi, const __nv_bfloat16* __restrict__ qlo,
    const __nv_bfloat16* __restrict__ khi, const __nv_bfloat16* __restrict__ klo,
    const __nv_bfloat16* __restrict__ vthi, const __nv_bfloat16* __restrict__ vtlo) {
  extern __shared__ char sm[];
  const int tid = threadIdx.x;
  const int wid = tid >> 5, lane = tid & 31;
  const int g = lane >> 2, q = lane & 3;
  const int bx = blockIdx.x;
  const int qt = bx & 7, h = (bx >> 3) & 31, b = bx >> 8;
  const int q0 = qt * AQ;
  const size_t bhq = (size_t)b * NH + h;
  const size_t bhk = (size_t)b * HKV + (h >> 2);

  // Q fragments (bf16 hi/lo), rows wid*16+g / +8
  uint32_t qa_h[8][4], qa_l[8][4];
  {
    const char* qh_ = (const char*)(qhi + (bhq * TT + q0 + wid * 16) * HD);
    const char* ql_ = (const char*)(qlo + (bhq * TT + q0 + wid * 16) * HD);
#pragma unroll
    for (int kc = 0; kc < 8; kc++) {
      int c0 = kc * 32 + q * 4;
      qa_h[kc][0] = *(const uint32_t*)(qh_ + g * 256 + c0);
      qa_h[kc][1] = *(const uint32_t*)(qh_ + (g + 8) * 256 + c0);
      qa_h[kc][2] = *(const uint32_t*)(qh_ + g * 256 + c0 + 16);
      qa_h[kc][3] = *(const uint32_t*)(qh_ + (g + 8) * 256 + c0 + 16);
      qa_l[kc][0] = *(const uint32_t*)(ql_ + g * 256 + c0);
      qa_l[kc][1] = *(const uint32_t*)(ql_ + (g + 8) * 256 + c0);
      qa_l[kc][2] = *(const uint32_t*)(ql_ + g * 256 + c0 + 16);
      qa_l[kc][3] = *(const uint32_t*)(ql_ + (g + 8) * 256 + c0 + 16);
    }
  }

  float ctx[16][4];
#pragma unroll
  for (int ni = 0; ni < 16; ni++)
#pragma unroll
    for (int r = 0; r < 4; r++) ctx[ni][r] = 0.f;
  float m0 = -1e30f, m1 = -1e30f, l0 = 0.f, l1 = 0.f;

  const int diag = LPREV + q0;
  const int ntiles = (diag + AQ) >> 6;
  const int row0 = wid * 16 + g, row1 = row0 + 8;

  attn_stage(sm, 0, khi, klo, vthi, vtlo, bhk, 0, tid);
  __syncthreads();

  for (int jt = 0; jt < ntiles; jt++) {
    const int j0 = jt << 6;
    if (jt + 1 < ntiles)
      attn_stage(sm, (jt + 1) & 1, khi, klo, vthi, vtlo, bhk, j0 + 64, tid);

    char* bK = sm + (jt & 1) * ABUF;
    char* bV = bK + 2 * KMAT;

    // ---- QK^T ----
    float s[8][4];
#pragma unroll
    for (int ni = 0; ni < 8; ni++)
#pragma unroll
      for (int r = 0; r < 4; r++) s[ni][r] = 0.f;

#pragma unroll
    for (int ni = 0; ni < 8; ni++) {
      const char* kr = bK + (ni * 8 + g) * KPB + q * 4;
      const char* krl = kr + KMAT;
#pragma unroll
      for (int kc = 0; kc < 8; kc++) {
        uint32_t bh0 = *(const uint32_t*)(kr + kc * 32);
        uint32_t bh1 = *(const uint32_t*)(kr + kc * 32 + 16);
        uint32_t bl0 = *(const uint32_t*)(krl + kc * 32);
        uint32_t bl1 = *(const uint32_t*)(krl + kc * 32 + 16);
        mma_bf16(s[ni], qa_h[kc][0], qa_h[kc][1], qa_h[kc][2], qa_h[kc][3], bh0, bh1);
        mma_bf16(s[ni], qa_l[kc][0], qa_l[kc][1], qa_l[kc][2], qa_l[kc][3], bh0, bh1);
        mma_bf16(s[ni], qa_h[kc][0], qa_h[kc][1], qa_h[kc][2], qa_h[kc][3], bl0, bl1);
      }
    }

    // ---- causal mask (partial tiles only) ----
    if (j0 + 63 > diag) {
#pragma unroll
      for (int ni = 0; ni < 8; ni++) {
        int key = j0 + ni * 8 + 2 * q;
        if (key > diag + row0) s[ni][0] = -1e30f;
        if (key + 1 > diag + row0) s[ni][1] = -1e30f;
        if (key > diag + row1) s[ni][2] = -1e30f;
        if (key + 1 > diag + row1) s[ni][3] = -1e30f;
      }
    }

    // ---- online softmax (rows row0, row1; 4 lanes per row) ----
    float rx0 = -1e30f, rx1 = -1e30f;
#pragma unroll
    for (int ni = 0; ni < 8; ni++) {
      rx0 = fmaxf(rx0, fmaxf(s[ni][0], s[ni][1]));
      rx1 = fmaxf(rx1, fmaxf(s[ni][2], s[ni][3]));
    }
    rx0 = fmaxf(rx0, __shfl_xor_sync(0xffffffffu, rx0, 1));
    rx0 = fmaxf(rx0, __shfl_xor_sync(0xffffffffu, rx0, 2));
    rx1 = fmaxf(rx1, __shfl_xor_sync(0xffffffffu, rx1, 1));
    rx1 = fmaxf(rx1, __shfl_xor_sync(0xffffffffu, rx1, 2));
    float nm0 = fmaxf(m0, rx0), nm1 = fmaxf(m1, rx1);
    float cr0 = __expf(m0 - nm0), cr1 = __expf(m1 - nm1);
    float sum0 = 0.f, sum1 = 0.f;
#pragma unroll
    for (int ni = 0; ni < 8; ni++) {
      s[ni][0] = __expf(s[ni][0] - nm0);
      s[ni][1] = __expf(s[ni][1] - nm0);
      s[ni][2] = __expf(s[ni][2] - nm1);
      s[ni][3] = __expf(s[ni][3] - nm1);
      sum0 += s[ni][0] + s[ni][1];
      sum1 += s[ni][2] + s[ni][3];
    }
    sum0 += __shfl_xor_sync(0xffffffffu, sum0, 1);
    sum0 += __shfl_xor_sync(0xffffffffu, sum0, 2);
    sum1 += __shfl_xor_sync(0xffffffffu, sum1, 1);
    sum1 += __shfl_xor_sync(0xffffffffu, sum1, 2);
    l0 = l0 * cr0 + sum0;
    l1 = l1 * cr1 + sum1;
    m0 = nm0;
    m1 = nm1;

    // ---- pack P into bf16 hi/lo A-fragments (key chunks of 16) ----
    uint32_t ph[4][4], pl[4][4];
#pragma unroll
    for (int cc = 0; cc < 4; cc++) {
      float v00 = s[2 * cc][0], v01 = s[2 * cc][1];
      float v10 = s[2 * cc][2], v11 = s[2 * cc][3];
      float v20 = s[2 * cc + 1][0], v21 = s[2 * cc + 1][1];
      float v30 = s[2 * cc + 1][2], v31 = s[2 * cc + 1][3];
      ph[cc][0] = pack_bf2(v00, v01);
      ph[cc][1] = pack_bf2(v10, v11);
      ph[cc][2] = pack_bf2(v20, v21);
      ph[cc][3] = pack_bf2(v30, v31);
      __nv_bfloat162 t0 = *(__nv_bfloat162*)&ph[cc][0];
      __nv_bfloat162 t1 = *(__nv_bfloat162*)&ph[cc][1];
      __nv_bfloat162 t2 = *(__nv_bfloat162*)&ph[cc][2];
      __nv_bfloat162 t3 = *(__nv_bfloat162*)&ph[cc][3];
      pl[cc][0] = pack_bf2(v00 - __bfloat162float(t0.x), v01 - __bfloat162float(t0.y));
      pl[cc][1] = pack_bf2(v10 - __bfloat162float(t1.x), v11 - __bfloat162float(t1.y));
      pl[cc][2] = pack_bf2(v20 - __bfloat162float(t2.x), v21 - __bfloat162float(t2.y));
      pl[cc][3] = pack_bf2(v30 - __bfloat162float(t3.x), v31 - __bfloat162float(t3.y));
    }

    // ---- rescale ctx ----
#pragma unroll
    for (int ni = 0; ni < 16; ni++) {
      ctx[ni][0] *= cr0; ctx[ni][1] *= cr0;
      ctx[ni][2] *= cr1; ctx[ni][3] *= cr1;
    }

    // ---- P * V ----
#pragma unroll
    for (int ni = 0; ni < 16; ni++) {
      const char* vr = bV + (ni * 8 + g) * VPB + q * 4;
      const char* vrl = vr + VMAT;
#pragma unroll
      for (int cc = 0; cc < 4; cc++) {
        uint32_t bh0 = *(const uint32_t*)(vr + cc * 32);
        uint32_t bh1 = *(const uint32_t*)(vr + cc * 32 + 16);
        uint32_t bl0 = *(const uint32_t*)(vrl + cc * 32);
        uint32_t bl1 = *(const uint32_t*)(vrl + cc * 32 + 16);
        mma_bf16(ctx[ni], ph[cc][0], ph[cc][1], ph[cc][2], ph[cc][3], bh0, bh1);
        mma_bf16(ctx[ni], pl[cc][0], pl[cc][1], pl[cc][2], pl[cc][3], bh0, bh1);
        mma_bf16(ctx[ni], ph[cc][0], ph[cc][1], ph[cc][2], ph[cc][3], bl0, bl1);
      }
    }
    __syncthreads();
  }

  // ---- epilogue ----
  float inv0 = 1.f / l0, inv1 = 1.f / l1;
  float* op0 = g_ctx + ((size_t)b * TT + q0 + row0) * (NH * HD) + h * HD;
  float* op1 = g_ctx + ((size_t)b * TT + q0 + row1) * (NH * HD) + h * HD;
#pragma unroll
  for (int ni = 0; ni < 16; ni++) {
    *(float2*)(op0 + ni * 8 + 2 * q) = make_float2(ctx[ni][0] * inv0, ctx[ni][1] * inv0);
    *(float2*)(op1 + ni * 8 + 2 * q) = make_float2(ctx[ni][2] * inv1, ctx[ni][3] * inv1);
  }
}

// ---------------- launch ------------------------------------------------------
extern "C" void kernel_launch(void* const* d_in, const int* in_sizes, int n_in,
                              void* d_out, int out_size) {
  const float* x = (const float*)d_in[0];
  const float* cosT = (const float*)d_in[2];
  const float* sinT = (const float*)d_in[3];
  const float* prev_k = (const float*)d_in[5];
  const float* prev_v = (const float*)d_in[6];
  const float* Wq = (const float*)d_in[7];
  const float* Wk = (const float*)d_in[8];
  const float* Wv = (const float*)d_in[9];
  const float* Wo = (const float*)d_in[10];
  const float* qw = (const float*)d_in[11];
  const float* kw = (const float*)d_in[12];

  float* out = (float*)d_out;
  const size_t out_elems = (size_t)BB * TT * DIN;
  const size_t kv_elems = (size_t)BB * HKV * LFULL * HD;

  float* fullk;
  float* fullv;
  if ((size_t)out_size >= out_elems + 2 * kv_elems) {
    fullk = out + out_elems;
    fullv = fullk + kv_elems;
  } else {
    cudaGetSymbolAddress((void**)&fullk, g_fk);
    cudaGetSymbolAddress((void**)&fullv, g_fv);
  }

  float *qraw, *kraw, *vraw, *ctx;
  __nv_bfloat16 *qhi, *qlo, *khi, *klo, *vthi, *vtlo;
  cudaGetSymbolAddress((void**)&qraw, g_qraw);
  cudaGetSymbolAddress((void**)&kraw, g_kraw);
  cudaGetSymbolAddress((void**)&vraw, g_vraw);
  cudaGetSymbolAddress((void**)&ctx, g_ctx);
  cudaGetSymbolAddress((void**)&qhi, g_qhi);
  cudaGetSymbolAddress((void**)&qlo, g_qlo);
  cudaGetSymbolAddress((void**)&khi, g_khi);
  cudaGetSymbolAddress((void**)&klo, g_klo);
  cudaGetSymbolAddress((void**)&vthi, g_vthi);
  cudaGetSymbolAddress((void**)&vtlo, g_vtlo);

  const int M = BB * TT;  // 2048

  cudaFuncSetAttribute(gemm_mma, cudaFuncAttributeMaxDynamicSharedMemorySize, GEMM_SMEM);
  cudaFuncSetAttribute(attn_mma, cudaFuncAttributeMaxDynamicSharedMemorySize, ATTN_SMEM);

  gemm_mma<<<dim3((NH * HD) / 128, M / 128), 256, GEMM_SMEM>>>(x, Wq, qraw, M, NH * HD, DIN);
  gemm_mma<<<dim3((HKV * HD) / 128, M / 128), 256, GEMM_SMEM>>>(x, Wk, kraw, M, HKV * HD, DIN);
  gemm_mma<<<dim3((HKV * HD) / 128, M / 128), 256, GEMM_SMEM>>>(x, Wv, vraw, M, HKV * HD, DIN);

  copy_prev<<<2048, 256>>>((const float4*)prev_k, (const float4*)prev_v,
                           (float4*)fullk, (float4*)fullv, khi, klo);

  norm_rope_kernel<<<dim3(BB * TT, NH + 2 * HKV), 128>>>(cosT, sinT, qw, kw,
                                                         fullk, fullv, qhi, qlo, khi, klo);

  conv_vt<<<dim3(LFULL / 32, HD / 32, BB * HKV), dim3(32, 8)>>>(fullv, vthi, vtlo);

  attn_mma<<<BB * NH * (TT / AQ), 256, ATTN_SMEM>>>(qhi, qlo, khi, klo, vthi, vtlo);

  gemm_mma<<<dim3(DIN / 128, M / 128), 256, GEMM_SMEM>>>(ctx, Wo, out, M, DIN, NH * HD);
}

// round 10
// speedup vs baseline: 3.7443x; 1.1714x over previous
#include <cuda_runtime.h>
#include <cuda_bf16.h>
#include <math.h>
#include <cstdint>

#define BB 2
#define TT 1024
#define DIN 2048
#define NH 32
#define HKV 8
#define HD 128
#define LPREV 1024
#define LFULL 2048

// ---------------- scratch ----------------------------------------------------
__device__ float g_qraw[(size_t)BB * TT * NH * HD];
__device__ float g_kraw[(size_t)BB * TT * HKV * HD];
__device__ float g_vraw[(size_t)BB * TT * HKV * HD];
__device__ float g_ctx[(size_t)BB * TT * NH * HD];
__device__ float g_fk[(size_t)BB * HKV * LFULL * HD];
__device__ float g_fv[(size_t)BB * HKV * LFULL * HD];
__device__ __nv_bfloat16 g_qhi[(size_t)BB * NH * TT * HD];
__device__ __nv_bfloat16 g_qlo[(size_t)BB * NH * TT * HD];
__device__ __nv_bfloat16 g_khi[(size_t)BB * HKV * LFULL * HD];
__device__ __nv_bfloat16 g_klo[(size_t)BB * HKV * LFULL * HD];
__device__ __nv_bfloat16 g_vthi[(size_t)BB * HKV * HD * LFULL];  // [bh][d][key]
__device__ __nv_bfloat16 g_vtlo[(size_t)BB * HKV * HD * LFULL];

// ---------------- helpers -----------------------------------------------------
__device__ __forceinline__ uint32_t smem_u32(const void* p) {
  uint32_t a;
  asm("{ .reg .u64 t; cvta.to.shared.u64 t, %1; cvt.u32.u64 %0, t; }" : "=r"(a) : "l"(p));
  return a;
}
#define CP_ASYNC16(dst_u32, src) \
  asm volatile("cp.async.cg.shared.global [%0], [%1], 16;" :: "r"(dst_u32), "l"(src))
#define CP_COMMIT() asm volatile("cp.async.commit_group;" ::: "memory")
#define CP_WAIT0() asm volatile("cp.async.wait_group 0;" ::: "memory")
#define CP_WAIT1() asm volatile("cp.async.wait_group 1;" ::: "memory")

__device__ __forceinline__ void mma_bf16(float* c, uint32_t a0, uint32_t a1,
                                         uint32_t a2, uint32_t a3,
                                         uint32_t b0, uint32_t b1) {
  asm volatile(
      "mma.sync.aligned.m16n8k16.row.col.f32.bf16.bf16.f32 "
      "{%0,%1,%2,%3}, {%4,%5,%6,%7}, {%8,%9}, {%0,%1,%2,%3};"
      : "+f"(c[0]), "+f"(c[1]), "+f"(c[2]), "+f"(c[3])
      : "r"(a0), "r"(a1), "r"(a2), "r"(a3), "r"(b0), "r"(b1));
}

__device__ __forceinline__ uint32_t pack_bf2(float a, float b) {
  __nv_bfloat162 t = __floats2bfloat162_rn(a, b);
  return *(uint32_t*)&t;
}

// ---------------- mma.sync GEMM: C[M,N] = A[M,K] * W[N,K]^T ------------------
#define RSB 80
#define MATB 10240
#define BUFB 40960
#define GEMM_SMEM (2 * BUFB)

__device__ __forceinline__ void gemm_ldg(const float* __restrict__ A,
                                         const float* __restrict__ W,
                                         float4* pf, int m0, int n0, int K,
                                         int k0, int tid) {
#pragma unroll
  for (int i = 0; i < 4; i++) {
    int c = tid + i * 256;
    int mat = c >> 9;
    int idx = c & 511;
    int row = idx >> 2;
    int kc = idx & 3;
    const float* gp = (mat ? W + (size_t)(n0 + row) * K
                           : A + (size_t)(m0 + row) * K) + k0 + kc * 8;
    pf[2 * i] = *(const float4*)gp;
    pf[2 * i + 1] = *(const float4*)(gp + 4);
  }
}

__device__ __forceinline__ void gemm_sts(const float4* pf, char* sm, int buf, int tid) {
  char* base = sm + buf * BUFB;
#pragma unroll
  for (int i = 0; i < 4; i++) {
    int c = tid + i * 256;
    int mat = c >> 9;
    int idx = c & 511;
    int row = idx >> 2;
    int kc = idx & 3;
    float v[8] = {pf[2 * i].x, pf[2 * i].y, pf[2 * i].z, pf[2 * i].w,
                  pf[2 * i + 1].x, pf[2 * i + 1].y, pf[2 * i + 1].z, pf[2 * i + 1].w};
    union { __nv_bfloat162 h2[4]; float4 f4; } hi, lo;
#pragma unroll
    for (int j = 0; j < 4; j++) {
      float a0 = v[2 * j], a1 = v[2 * j + 1];
      __nv_bfloat16 h0 = __float2bfloat16(a0);
      __nv_bfloat16 h1 = __float2bfloat16(a1);
      hi.h2[j] = __nv_bfloat162(h0, h1);
      lo.h2[j] = __floats2bfloat162_rn(a0 - __bfloat162float(h0),
                                       a1 - __bfloat162float(h1));
    }
    char* mb = base + mat * (2 * MATB) + row * RSB + kc * 16;
    *(float4*)mb = hi.f4;
    *(float4*)(mb + MATB) = lo.f4;
  }
}

__global__ __launch_bounds__(256) void gemm_mma(const float* __restrict__ A,
                                                const float* __restrict__ W,
                                                float* __restrict__ C,
                                                int M, int N, int K) {
  extern __shared__ char sm[];
  const int tid = threadIdx.x;
  const int wid = tid >> 5, lane = tid & 31;
  const int m0 = blockIdx.y * 128, n0 = blockIdx.x * 128;
  const int wr = wid >> 1, wc = wid & 1;
  const int g = lane >> 2, q = lane & 3;

  float acc[2][8][4];
#pragma unroll
  for (int mi = 0; mi < 2; mi++)
#pragma unroll
    for (int ni = 0; ni < 8; ni++)
#pragma unroll
      for (int r = 0; r < 4; r++) acc[mi][ni][r] = 0.f;

  float4 pf[8];
  gemm_ldg(A, W, pf, m0, n0, K, 0, tid);
  gemm_sts(pf, sm, 0, tid);
  __syncthreads();

  const int nstage = K >> 5;
  for (int s = 0; s < nstage; s++) {
    if (s + 1 < nstage)
      gemm_ldg(A, W, pf, m0, n0, K, (s + 1) << 5, tid);  // LDG issued, latency hidden

    char* bufb = sm + (s & 1) * BUFB;
#pragma unroll
    for (int ks = 0; ks < 2; ks++) {
      const int kb = ks * 32 + q * 4;
      uint32_t ah[2][4], al[2][4];
#pragma unroll
      for (int mi = 0; mi < 2; mi++) {
        const char* ra = bufb + (wr * 32 + mi * 16 + g) * RSB + kb;
        ah[mi][0] = *(const uint32_t*)(ra);
        ah[mi][1] = *(const uint32_t*)(ra + 8 * RSB);
        ah[mi][2] = *(const uint32_t*)(ra + 16);
        ah[mi][3] = *(const uint32_t*)(ra + 8 * RSB + 16);
        al[mi][0] = *(const uint32_t*)(ra + MATB);
        al[mi][1] = *(const uint32_t*)(ra + MATB + 8 * RSB);
        al[mi][2] = *(const uint32_t*)(ra + MATB + 16);
        al[mi][3] = *(const uint32_t*)(ra + MATB + 8 * RSB + 16);
      }
#pragma unroll
      for (int ni = 0; ni < 8; ni++) {
        const char* rb = bufb + 2 * MATB + (wc * 64 + ni * 8 + g) * RSB + kb;
        uint32_t bh0 = *(const uint32_t*)(rb);
        uint32_t bh1 = *(const uint32_t*)(rb + 16);
        uint32_t bl0 = *(const uint32_t*)(rb + MATB);
        uint32_t bl1 = *(const uint32_t*)(rb + MATB + 16);
#pragma unroll
        for (int mi = 0; mi < 2; mi++) {
          mma_bf16(acc[mi][ni], ah[mi][0], ah[mi][1], ah[mi][2], ah[mi][3], bh0, bh1);
          mma_bf16(acc[mi][ni], al[mi][0], al[mi][1], al[mi][2], al[mi][3], bh0, bh1);
          mma_bf16(acc[mi][ni], ah[mi][0], ah[mi][1], ah[mi][2], ah[mi][3], bl0, bl1);
        }
      }
    }
    if (s + 1 < nstage)
      gemm_sts(pf, sm, (s + 1) & 1, tid);  // convert + STS after compute
    __syncthreads();
  }

#pragma unroll
  for (int mi = 0; mi < 2; mi++) {
    const int r = m0 + wr * 32 + mi * 16 + g;
#pragma unroll
    for (int ni = 0; ni < 8; ni++) {
      const int c0 = n0 + wc * 64 + ni * 8 + q * 2;
      *(float2*)(C + (size_t)r * N + c0) = make_float2(acc[mi][ni][0], acc[mi][ni][1]);
      *(float2*)(C + (size_t)(r + 8) * N + c0) = make_float2(acc[mi][ni][2], acc[mi][ni][3]);
    }
  }
}

// ---------------- copy prev_k/prev_v + K bf16 split ---------------------------
__global__ void copy_prev(const float4* __restrict__ pk, const float4* __restrict__ pv,
                          float4* __restrict__ fk, float4* __restrict__ fv,
                          __nv_bfloat16* __restrict__ khi, __nv_bfloat16* __restrict__ klo) {
  int i = blockIdx.x * blockDim.x + threadIdx.x;
  const int total = BB * HKV * LPREV * HD / 4;
  if (i >= total) return;
  const int per = LPREV * HD / 4;
  const int dper = LFULL * HD / 4;
  int bh = i / per, off = i - bh * per;
  float4 kv = pk[i];
  fk[(size_t)bh * dper + off] = kv;
  fv[(size_t)bh * dper + off] = pv[i];
  float v[4] = {kv.x, kv.y, kv.z, kv.w};
  union { __nv_bfloat16 h[4]; uint2 u; } H, L;
#pragma unroll
  for (int j = 0; j < 4; j++) {
    H.h[j] = __float2bfloat16(v[j]);
    L.h[j] = __float2bfloat16(v[j] - __bfloat162float(H.h[j]));
  }
  size_t kb = (size_t)bh * LFULL * HD + (size_t)off * 4;
  *(uint2*)(khi + kb) = H.u;
  *(uint2*)(klo + kb) = L.u;
}

// ---------------- RMSNorm + RoPE + scatter (+ bf16 splits) --------------------
__global__ void norm_rope_kernel(const float* __restrict__ cosT,
                                 const float* __restrict__ sinT,
                                 const float* __restrict__ qw,
                                 const float* __restrict__ kw,
                                 float* __restrict__ fullk,
                                 float* __restrict__ fullv,
                                 __nv_bfloat16* __restrict__ qhi,
                                 __nv_bfloat16* __restrict__ qlo,
                                 __nv_bfloat16* __restrict__ khi,
                                 __nv_bfloat16* __restrict__ klo) {
  int bt = blockIdx.x;
  int b = bt >> 10, t = bt & 1023;
  int role = blockIdx.y;
  int d = threadIdx.x;
  __shared__ float red[128];
  __shared__ float row[128];
  int pos = LPREV + t;
  const float scale = 0.08838834764831845f;  // 1/sqrt(128)

  if (role < NH) {
    int h = role;
    float v = g_qraw[(size_t)bt * (NH * HD) + h * HD + d];
    red[d] = v * v;
    __syncthreads();
#pragma unroll
    for (int s = 64; s > 0; s >>= 1) {
      if (d < s) red[d] += red[d + s];
      __syncthreads();
    }
    float inv = rsqrtf(red[0] * (1.0f / HD) + 1e-6f);
    float xn = v * inv * qw[d];
    row[d] = xn;
    __syncthreads();
    float rot = (d < 64) ? -row[d + 64] : row[d - 64];
    float o = (xn * cosT[pos * HD + d] + rot * sinT[pos * HD + d]) * scale;
    __nv_bfloat16 hh = __float2bfloat16(o);
    size_t qi = (((size_t)b * NH + h) * TT + t) * HD + d;
    qhi[qi] = hh;
    qlo[qi] = __float2bfloat16(o - __bfloat162float(hh));
  } else if (role < NH + HKV) {
    int h = role - NH;
    float v = g_kraw[(size_t)bt * (HKV * HD) + h * HD + d];
    red[d] = v * v;
    __syncthreads();
#pragma unroll
    for (int s = 64; s > 0; s >>= 1) {
      if (d < s) red[d] += red[d + s];
      __syncthreads();
    }
    float inv = rsqrtf(red[0] * (1.0f / HD) + 1e-6f);
    float xn = v * inv * kw[d];
    row[d] = xn;
    __syncthreads();
    float rot = (d < 64) ? -row[d + 64] : row[d - 64];
    float o = xn * cosT[pos * HD + d] + rot * sinT[pos * HD + d];
    size_t ki = (((size_t)b * HKV + h) * LFULL + LPREV + t) * HD + d;
    fullk[ki] = o;
    __nv_bfloat16 hh = __float2bfloat16(o);
    khi[ki] = hh;
    klo[ki] = __float2bfloat16(o - __bfloat162float(hh));
  } else {
    int h = role - NH - HKV;
    fullv[(((size_t)b * HKV + h) * LFULL + LPREV + t) * HD + d] =
        g_vraw[(size_t)bt * (HKV * HD) + h * HD + d];
  }
}

// ---------------- V transpose + bf16 split: fullv -> [bh][d][key] -------------
__global__ void conv_vt(const float* __restrict__ fv,
                        __nv_bfloat16* __restrict__ vthi,
                        __nv_bfloat16* __restrict__ vtlo) {
  __shared__ float tbuf[32][33];
  int bh = blockIdx.z;
  int k0 = blockIdx.x * 32, d0 = blockIdx.y * 32;
  int tx = threadIdx.x, ty = threadIdx.y;  // 32 x 8
#pragma unroll
  for (int i = 0; i < 4; i++)
    tbuf[ty + 8 * i][tx] = fv[((size_t)bh * LFULL + k0 + ty + 8 * i) * HD + d0 + tx];
  __syncthreads();
#pragma unroll
  for (int i = 0; i < 4; i++) {
    float v = tbuf[tx][ty + 8 * i];
    __nv_bfloat16 hh = __float2bfloat16(v);
    size_t oi = ((size_t)bh * HD + d0 + ty + 8 * i) * LFULL + k0 + tx;
    vthi[oi] = hh;
    vtlo[oi] = __float2bfloat16(v - __bfloat162float(hh));
  }
}

// ---------------- tensor-core flash attention ---------------------------------
// 256 thr, 128 q-rows, 64-key tiles, cp.async double buffer, Q in smem.
#define AQ 128
#define KPB 272
#define VPB 144
#define QPB 272
#define KMAT (64 * KPB)               // 17408
#define VMAT (128 * VPB)              // 18432
#define QMAT (128 * QPB)              // 34816
#define ABUF (2 * KMAT + 2 * VMAT)    // 71680
#define ATTN_SMEM (2 * ABUF + 2 * QMAT)  // 212992

__device__ __forceinline__ void attn_stage_async(uint32_t smb, int buf,
                                                 const __nv_bfloat16* khi,
                                                 const __nv_bfloat16* klo,
                                                 const __nv_bfloat16* vthi,
                                                 const __nv_bfloat16* vtlo,
                                                 size_t bhk, int j0, int tid) {
  uint32_t base = smb + buf * ABUF;
#pragma unroll
  for (int i = 0; i < 16; i++) {
    int idx = tid + i * 256;
    int mat = idx >> 10;
    int x = idx & 1023;
    if (mat < 2) {
      int row = x >> 4, c = x & 15;
      const __nv_bfloat16* src = (mat ? klo : khi) + (bhk * LFULL + j0 + row) * HD + c * 8;
      CP_ASYNC16(base + mat * KMAT + row * KPB + c * 16, src);
    } else {
      int row = x >> 3, c = x & 7;
      const __nv_bfloat16* src = (mat == 3 ? vtlo : vthi) + (bhk * HD + row) * LFULL + j0 + c * 8;
      CP_ASYNC16(base + 2 * KMAT + (mat - 2) * VMAT + row * VPB + c * 16, src);
    }
  }
}

__global__ __launch_bounds__(256, 1) void attn_mma(
    const __nv_bfloat16* __restrict__ qhi, const __nv_bfloat16* __restrict__ qlo,
    const __nv_bfloat16* __restrict__ khi, const __nv_bfloat16* __restrict__ klo,
    const __nv_bfloat16* __restrict__ vthi, const __nv_bfloat16* __restrict__ vtlo) {
  extern __shared__ char sm[];
  const uint32_t smb = smem_u32(sm);
  const int tid = threadIdx.x;
  const int wid = tid >> 5, lane = tid & 31;
  const int g = lane >> 2, q = lane & 3;
  const int bx = blockIdx.x;
  const int qt = bx & 7, h = (bx >> 3) & 31, b = bx >> 8;
  const int q0 = qt * AQ;
  const size_t bhq = (size_t)b * NH + h;
  const size_t bhk = (size_t)b * HKV + (h >> 2);

  // ---- prologue: Q (hi/lo) + stage 0 via cp.async, one group ----
  {
    const uint32_t qb = smb + 2 * ABUF;
#pragma unroll
    for (int i = 0; i < 16; i++) {
      int idx = tid + i * 256;
      int mat = idx >> 11;
      int x = idx & 2047;
      int row = x >> 4, c = x & 15;
      const __nv_bfloat16* src = (mat ? qlo : qhi) + (bhq * TT + q0 + row) * HD + c * 8;
      CP_ASYNC16(qb + mat * QMAT + row * QPB + c * 16, src);
    }
  }
  attn_stage_async(smb, 0, khi, klo, vthi, vtlo, bhk, 0, tid);
  CP_COMMIT();

  float ctx[16][4];
#pragma unroll
  for (int ni = 0; ni < 16; ni++)
#pragma unroll
    for (int r = 0; r < 4; r++) ctx[ni][r] = 0.f;
  float m0 = -1e30f, m1 = -1e30f, l0 = 0.f, l1 = 0.f;

  const int diag = LPREV + q0;
  const int ntiles = (diag + AQ) >> 6;
  const int row0 = wid * 16 + g, row1 = row0 + 8;
  const char* qrow_h = sm + 2 * ABUF + (wid * 16 + g) * QPB + q * 4;
  const char* qrow_l = qrow_h + QMAT;

  for (int jt = 0; jt < ntiles; jt++) {
    const int j0 = jt << 6;
    if (jt + 1 < ntiles) {
      attn_stage_async(smb, (jt + 1) & 1, khi, klo, vthi, vtlo, bhk, j0 + 64, tid);
      CP_COMMIT();
      CP_WAIT1();
    } else {
      CP_WAIT0();
    }
    __syncthreads();

    const char* bK = sm + (jt & 1) * ABUF;
    const char* bV = bK + 2 * KMAT;

    // ---- QK^T (kc outer: only 8 Q regs live) ----
    float s[8][4];
#pragma unroll
    for (int ni = 0; ni < 8; ni++)
#pragma unroll
      for (int r = 0; r < 4; r++) s[ni][r] = 0.f;

#pragma unroll
    for (int kc = 0; kc < 8; kc++) {
      const char* qh_ = qrow_h + kc * 32;
      const char* ql_ = qrow_l + kc * 32;
      uint32_t a0 = *(const uint32_t*)(qh_);
      uint32_t a1 = *(const uint32_t*)(qh_ + 8 * QPB);
      uint32_t a2 = *(const uint32_t*)(qh_ + 16);
      uint32_t a3 = *(const uint32_t*)(qh_ + 8 * QPB + 16);
      uint32_t c0 = *(const uint32_t*)(ql_);
      uint32_t c1 = *(const uint32_t*)(ql_ + 8 * QPB);
      uint32_t c2 = *(const uint32_t*)(ql_ + 16);
      uint32_t c3 = *(const uint32_t*)(ql_ + 8 * QPB + 16);
#pragma unroll
      for (int ni = 0; ni < 8; ni++) {
        const char* kr = bK + (ni * 8 + g) * KPB + kc * 32 + q * 4;
        uint32_t bh0 = *(const uint32_t*)(kr);
        uint32_t bh1 = *(const uint32_t*)(kr + 16);
        uint32_t bl0 = *(const uint32_t*)(kr + KMAT);
        uint32_t bl1 = *(const uint32_t*)(kr + KMAT + 16);
        mma_bf16(s[ni], a0, a1, a2, a3, bh0, bh1);
        mma_bf16(s[ni], c0, c1, c2, c3, bh0, bh1);
        mma_bf16(s[ni], a0, a1, a2, a3, bl0, bl1);
      }
    }

    // ---- causal mask ----
    if (j0 + 63 > diag) {
#pragma unroll
      for (int ni = 0; ni < 8; ni++) {
        int key = j0 + ni * 8 + 2 * q;
        if (key > diag + row0) s[ni][0] = -1e30f;
        if (key + 1 > diag + row0) s[ni][1] = -1e30f;
        if (key > diag + row1) s[ni][2] = -1e30f;
        if (key + 1 > diag + row1) s[ni][3] = -1e30f;
      }
    }

    // ---- online softmax ----
    float rx0 = -1e30f, rx1 = -1e30f;
#pragma unroll
    for (int ni = 0; ni < 8; ni++) {
      rx0 = fmaxf(rx0, fmaxf(s[ni][0], s[ni][1]));
      rx1 = fmaxf(rx1, fmaxf(s[ni][2], s[ni][3]));
    }
    rx0 = fmaxf(rx0, __shfl_xor_sync(0xffffffffu, rx0, 1));
    rx0 = fmaxf(rx0, __shfl_xor_sync(0xffffffffu, rx0, 2));
    rx1 = fmaxf(rx1, __shfl_xor_sync(0xffffffffu, rx1, 1));
    rx1 = fmaxf(rx1, __shfl_xor_sync(0xffffffffu, rx1, 2));
    float nm0 = fmaxf(m0, rx0), nm1 = fmaxf(m1, rx1);
    float cr0 = __expf(m0 - nm0), cr1 = __expf(m1 - nm1);
    float sum0 = 0.f, sum1 = 0.f;
#pragma unroll
    for (int ni = 0; ni < 8; ni++) {
      s[ni][0] = __expf(s[ni][0] - nm0);
      s[ni][1] = __expf(s[ni][1] - nm0);
      s[ni][2] = __expf(s[ni][2] - nm1);
      s[ni][3] = __expf(s[ni][3] - nm1);
      sum0 += s[ni][0] + s[ni][1];
      sum1 += s[ni][2] + s[ni][3];
    }
    sum0 += __shfl_xor_sync(0xffffffffu, sum0, 1);
    sum0 += __shfl_xor_sync(0xffffffffu, sum0, 2);
    sum1 += __shfl_xor_sync(0xffffffffu, sum1, 1);
    sum1 += __shfl_xor_sync(0xffffffffu, sum1, 2);
    l0 = l0 * cr0 + sum0;
    l1 = l1 * cr1 + sum1;
    m0 = nm0;
    m1 = nm1;

    // ---- pack P (hi/lo) ----
    uint32_t ph[4][4], pl[4][4];
#pragma unroll
    for (int cc = 0; cc < 4; cc++) {
      float v00 = s[2 * cc][0], v01 = s[2 * cc][1];
      float v10 = s[2 * cc][2], v11 = s[2 * cc][3];
      float v20 = s[2 * cc + 1][0], v21 = s[2 * cc + 1][1];
      float v30 = s[2 * cc + 1][2], v31 = s[2 * cc + 1][3];
      ph[cc][0] = pack_bf2(v00, v01);
      ph[cc][1] = pack_bf2(v10, v11);
      ph[cc][2] = pack_bf2(v20, v21);
      ph[cc][3] = pack_bf2(v30, v31);
      __nv_bfloat162 t0 = *(__nv_bfloat162*)&ph[cc][0];
      __nv_bfloat162 t1 = *(__nv_bfloat162*)&ph[cc][1];
      __nv_bfloat162 t2 = *(__nv_bfloat162*)&ph[cc][2];
      __nv_bfloat162 t3 = *(__nv_bfloat162*)&ph[cc][3];
      pl[cc][0] = pack_bf2(v00 - __bfloat162float(t0.x), v01 - __bfloat162float(t0.y));
      pl[cc][1] = pack_bf2(v10 - __bfloat162float(t1.x), v11 - __bfloat162float(t1.y));
      pl[cc][2] = pack_bf2(v20 - __bfloat162float(t2.x), v21 - __bfloat162float(t2.y));
      pl[cc][3] = pack_bf2(v30 - __bfloat162float(t3.x), v31 - __bfloat162float(t3.y));
    }

    // ---- rescale ctx ----
#pragma unroll
    for (int ni = 0; ni < 16; ni++) {
      ctx[ni][0] *= cr0; ctx[ni][1] *= cr0;
      ctx[ni][2] *= cr1; ctx[ni][3] *= cr1;
    }

    // ---- P * V ----
#pragma unroll
    for (int ni = 0; ni < 16; ni++) {
      const char* vr = bV + (ni * 8 + g) * VPB + q * 4;
#pragma unroll
      for (int cc = 0; cc < 4; cc++) {
        uint32_t bh0 = *(const uint32_t*)(vr + cc * 32);
        uint32_t bh1 = *(const uint32_t*)(vr + cc * 32 + 16);
        uint32_t bl0 = *(const uint32_t*)(vr + VMAT + cc * 32);
        uint32_t bl1 = *(const uint32_t*)(vr + VMAT + cc * 32 + 16);
        mma_bf16(ctx[ni], ph[cc][0], ph[cc][1], ph[cc][2], ph[cc][3], bh0, bh1);
        mma_bf16(ctx[ni], pl[cc][0], pl[cc][1], pl[cc][2], pl[cc][3], bh0, bh1);
        mma_bf16(ctx[ni], ph[cc][0], ph[cc][1], ph[cc][2], ph[cc][3], bl0, bl1);
      }
    }
    __syncthreads();
  }

  // ---- epilogue ----
  float inv0 = 1.f / l0, inv1 = 1.f / l1;
  float* op0 = g_ctx + ((size_t)b * TT + q0 + row0) * (NH * HD) + h * HD;
  float* op1 = g_ctx + ((size_t)b * TT + q0 + row1) * (NH * HD) + h * HD;
#pragma unroll
  for (int ni = 0; ni < 16; ni++) {
    *(float2*)(op0 + ni * 8 + 2 * q) = make_float2(ctx[ni][0] * inv0, ctx[ni][1] * inv0);
    *(float2*)(op1 + ni * 8 + 2 * q) = make_float2(ctx[ni][2] * inv1, ctx[ni][3] * inv1);
  }
}

// ---------------- launch ------------------------------------------------------
extern "C" void kernel_launch(void* const* d_in, const int* in_sizes, int n_in,
                              void* d_out, int out_size) {
  const float* x = (const float*)d_in[0];
  const float* cosT = (const float*)d_in[2];
  const float* sinT = (const float*)d_in[3];
  const float* prev_k = (const float*)d_in[5];
  const float* prev_v = (const float*)d_in[6];
  const float* Wq = (const float*)d_in[7];
  const float* Wk = (const float*)d_in[8];
  const float* Wv = (const float*)d_in[9];
  const float* Wo = (const float*)d_in[10];
  const float* qw = (const float*)d_in[11];
  const float* kw = (const float*)d_in[12];

  float* out = (float*)d_out;
  const size_t out_elems = (size_t)BB * TT * DIN;
  const size_t kv_elems = (size_t)BB * HKV * LFULL * HD;

  float* fullk;
  float* fullv;
  if ((size_t)out_size >= out_elems + 2 * kv_elems) {
    fullk = out + out_elems;
    fullv = fullk + kv_elems;
  } else {
    cudaGetSymbolAddress((void**)&fullk, g_fk);
    cudaGetSymbolAddress((void**)&fullv, g_fv);
  }

  float *qraw, *kraw, *vraw, *ctx;
  __nv_bfloat16 *qhi, *qlo, *khi, *klo, *vthi, *vtlo;
  cudaGetSymbolAddress((void**)&qraw, g_qraw);
  cudaGetSymbolAddress((void**)&kraw, g_kraw);
  cudaGetSymbolAddress((void**)&vraw, g_vraw);
  cudaGetSymbolAddress((void**)&ctx, g_ctx);
  cudaGetSymbolAddress((void**)&qhi, g_qhi);
  cudaGetSymbolAddress((void**)&qlo, g_qlo);
  cudaGetSymbolAddress((void**)&khi, g_khi);
  cudaGetSymbolAddress((void**)&klo, g_klo);
  cudaGetSymbolAddress((void**)&vthi, g_vthi);
  cudaGetSymbolAddress((void**)&vtlo, g_vtlo);

  const int M = BB * TT;  // 2048

  cudaFuncSetAttribute(gemm_mma, cudaFuncAttributeMaxDynamicSharedMemorySize, GEMM_SMEM);
  cudaFuncSetAttribute(attn_mma, cudaFuncAttributeMaxDynamicSharedMemorySize, ATTN_SMEM);

  gemm_mma<<<dim3((NH * HD) / 128, M / 128), 256, GEMM_SMEM>>>(x, Wq, qraw, M, NH * HD, DIN);
  gemm_mma<<<dim3((HKV * HD) / 128, M / 128), 256, GEMM_SMEM>>>(x, Wk, kraw, M, HKV * HD, DIN);
  gemm_mma<<<dim3((HKV * HD) / 128, M / 128), 256, GEMM_SMEM>>>(x, Wv, vraw, M, HKV * HD, DIN);

  copy_prev<<<2048, 256>>>((const float4*)prev_k, (const float4*)prev_v,
                           (float4*)fullk, (float4*)fullv, khi, klo);

  norm_rope_kernel<<<dim3(BB * TT, NH + 2 * HKV), 128>>>(cosT, sinT, qw, kw,
                                                         fullk, fullv, qhi, qlo, khi, klo);

  conv_vt<<<dim3(LFULL / 32, HD / 32, BB * HKV), dim3(32, 8)>>>(fullv, vthi, vtlo);

  attn_mma<<<BB * NH * (TT / AQ), 256, ATTN_SMEM>>>(qhi, qlo, khi, klo, vthi, vtlo);

  gemm_mma<<<dim3(DIN / 128, M / 128), 256, GEMM_SMEM>>>(ctx, Wo, out, M, DIN, NH * HD);
}